// round 15
// baseline (speedup 1.0000x reference)
#include <cuda_runtime.h>
#include <cuda_fp16.h>
#include <math.h>
#include <stdint.h>

// ---------------- problem constants ----------------
#define BB     64
#define HH     56
#define WW     56
#define CC     192
#define NHEADS 6
#define HD     32
#define WSZ    7
#define TOK    49
#define BMS    50          // padded bias-table row stride
#define NWIN_I 64
#define SHIFT  3
#define NTOK   (BB*HH*WW)   // 200704
#define NWIN   (BB*NWIN_I)  // 4096
#define HIDDEN 768

// ---------------- scratch (device globals; zero-initialized, no allocs allowed) ----------------
__device__ __half g_xw  [(size_t)NTOK*CC];
__device__ __half g_qkv [(size_t)NTOK*3*CC];
__device__ __half g_att [(size_t)NTOK*CC];
__device__ __half g_proj[(size_t)NTOK*CC];
__device__ __half g_ln2 [(size_t)NTOK*CC];
__device__ __half g_hid [(size_t)NTOK*HIDDEN];
__device__ __half g_wqkv [3*CC*CC];
__device__ __half g_wproj[CC*CC];
__device__ __half g_wfc1 [HIDDEN*CC];
__device__ __half g_wfc2 [CC*HIDDEN];
__device__ __half g_bm  [NWIN_I*NHEADS*TOK*BMS];   // bias+mask table, f16, padded rows

// ---------------- helpers ----------------
__device__ __forceinline__ uint32_t smem_u32(const void* p) {
    uint32_t a;
    asm("{ .reg .u64 t; cvta.to.shared.u64 t, %1; cvt.u32.u64 %0, t; }" : "=r"(a) : "l"(p));
    return a;
}
__device__ __forceinline__ float gelu_exact(float x) {
    return 0.5f * x * (1.0f + erff(x * 0.70710678118654752f));
}
__device__ __forceinline__ void ldsm_x4(uint32_t* r, uint32_t addr) {
    asm volatile("ldmatrix.sync.aligned.m8n8.x4.shared.b16 {%0,%1,%2,%3}, [%4];"
                 : "=r"(r[0]), "=r"(r[1]), "=r"(r[2]), "=r"(r[3]) : "r"(addr));
}
__device__ __forceinline__ void mma16816f(float* d, const uint32_t* a, uint32_t b0, uint32_t b1) {
    asm volatile(
        "mma.sync.aligned.m16n8k16.row.col.f32.f16.f16.f32 "
        "{%0,%1,%2,%3}, {%4,%5,%6,%7}, {%8,%9}, {%0,%1,%2,%3};"
        : "+f"(d[0]), "+f"(d[1]), "+f"(d[2]), "+f"(d[3])
        : "r"(a[0]), "r"(a[1]), "r"(a[2]), "r"(a[3]), "r"(b0), "r"(b1));
}
__device__ __forceinline__ void mma16816h(uint32_t* d, const uint32_t* a, uint32_t b0, uint32_t b1) {
    asm volatile(
        "mma.sync.aligned.m16n8k16.row.col.f16.f16.f16.f16 "
        "{%0,%1}, {%2,%3,%4,%5}, {%6,%7}, {%0,%1};"
        : "+r"(d[0]), "+r"(d[1])
        : "r"(a[0]), "r"(a[1]), "r"(a[2]), "r"(a[3]), "r"(b0), "r"(b1));
}
__device__ __forceinline__ void cpasync16(uint32_t smem, const void* gptr) {
    asm volatile("cp.async.cg.shared.global [%0], [%1], 16;" :: "r"(smem), "l"(gptr));
}
__device__ __forceinline__ void cpasync_commit() {
    asm volatile("cp.async.commit_group;" ::: "memory");
}
template<int N> __device__ __forceinline__ void cpasync_wait() {
    asm volatile("cp.async.wait_group %0;" :: "n"(N) : "memory");
}

// ---------------- all weights f32 -> f16 in one launch ----------------
#define NW_QKV (3*CC*CC)
#define NW_PRJ (CC*CC)
#define NW_FC1 (HIDDEN*CC)
#define NW_FC2 (CC*HIDDEN)
#define NW_ALL (NW_QKV+NW_PRJ+NW_FC1+NW_FC2)

__global__ void k_f2h_all(const float* __restrict__ qkv_w, const float* __restrict__ proj_w,
                          const float* __restrict__ fc1_w, const float* __restrict__ fc2_w) {
    int i = blockIdx.x * 256 + threadIdx.x;
    if (i < NW_QKV) { g_wqkv[i] = __float2half(qkv_w[i]); return; }
    i -= NW_QKV;
    if (i < NW_PRJ) { g_wproj[i] = __float2half(proj_w[i]); return; }
    i -= NW_PRJ;
    if (i < NW_FC1) { g_wfc1[i] = __float2half(fc1_w[i]); return; }
    i -= NW_FC1;
    if (i < NW_FC2) { g_wfc2[i] = __float2half(fc2_w[i]); }
}

// ---------------- precompute bias+mask table (f16, padded rows; col 49 = -30000) ----------------
__global__ void k_bias(const float* __restrict__ rpb, const int* __restrict__ relidx,
                       const float* __restrict__ amask) {
    int wh = blockIdx.x;
    int win = wh / NHEADS, h = wh % NHEADS;
    for (int i = threadIdx.x; i < TOK*BMS; i += 256) {
        int r = i / BMS, t = i % BMS;
        float v = (t < TOK)
            ? rpb[relidx[r*TOK + t] * NHEADS + h] + amask[win * (TOK*TOK) + r*TOK + t]
            : -30000.0f;
        g_bm[(size_t)wh * (TOK*BMS) + i] = __float2half(v);
    }
}

// ---------------- LN1 + roll + window partition: warp-per-token ----------------
__global__ void __launch_bounds__(256) k_ln1_shift_part(const float* __restrict__ x,
                                 const float* __restrict__ g,
                                 const float* __restrict__ b) {
    int lane = threadIdx.x & 31, warp = threadIdx.x >> 5;
    int w = blockIdx.x * 8 + warp;
    int n = w / TOK, t = w % TOK;
    int img = n / NWIN_I, win = n % NWIN_I;
    int hs = (win / 8) * WSZ + t / WSZ;
    int ws = (win % 8) * WSZ + t % WSZ;
    int hsrc = (hs + SHIFT) % HH;
    int wsrc = (ws + SHIFT) % WW;
    const float* row = x + ((size_t)img * (HH*WW) + hsrc * WW + wsrc) * CC;

    float v[6];
    float s = 0.f, s2 = 0.f;
    #pragma unroll
    for (int j = 0; j < 6; j++) {
        v[j] = row[lane + 32*j];
        s += v[j]; s2 += v[j]*v[j];
    }
    #pragma unroll
    for (int o = 16; o > 0; o >>= 1) {
        s  += __shfl_xor_sync(0xffffffffu, s,  o);
        s2 += __shfl_xor_sync(0xffffffffu, s2, o);
    }
    float mean = s * (1.0f / CC);
    float var  = s2 * (1.0f / CC) - mean * mean;
    float inv  = rsqrtf(var + 1e-5f);
    __half* outp = g_xw + (size_t)w * CC;
    #pragma unroll
    for (int j = 0; j < 6; j++) {
        int c = lane + 32*j;
        outp[c] = __float2half((v[j] - mean) * inv * g[c] + b[c]);
    }
}

// ---------------- window reverse + roll + residual + LN2 (LN output ONLY) ----------------
__global__ void __launch_bounds__(256) k_ln2(const float* __restrict__ x,
                            const float* __restrict__ g,
                            const float* __restrict__ b) {
    int lane = threadIdx.x & 31, warp = threadIdx.x >> 5;
    int tok = blockIdx.x * 8 + warp;
    int img = tok / (HH*WW);
    int hw  = tok % (HH*WW);
    int hh = hw / WW, ww = hw % WW;
    int hs = (hh + HH - SHIFT) % HH;
    int ws = (ww + WW - SHIFT) % WW;
    int win = (hs / WSZ) * 8 + (ws / WSZ);
    int t   = (hs % WSZ) * WSZ + (ws % WSZ);
    const __half* prow = g_proj + ((size_t)(img * NWIN_I + win) * TOK + t) * CC;
    const float* xrow = x + (size_t)tok * CC;

    float v[6];
    float s = 0.f, s2 = 0.f;
    #pragma unroll
    for (int j = 0; j < 6; j++) {
        int c = lane + 32*j;
        v[j] = xrow[c] + __half2float(prow[c]);
        s += v[j]; s2 += v[j]*v[j];
    }
    #pragma unroll
    for (int o = 16; o > 0; o >>= 1) {
        s  += __shfl_xor_sync(0xffffffffu, s,  o);
        s2 += __shfl_xor_sync(0xffffffffu, s2, o);
    }
    float mean = s * (1.0f / CC);
    float var  = s2 * (1.0f / CC) - mean * mean;
    float inv  = rsqrtf(var + 1e-5f);
    __half* outp = g_ln2 + (size_t)tok * CC;
    #pragma unroll
    for (int j = 0; j < 6; j++) {
        int c = lane + 32*j;
        outp[c] = __float2half((v[j] - mean) * inv * g[c] + b[c]);
    }
}

// ---------------- BIG-TILE GEMM: BM=256, BN=128, warp tile 64x64, f16 accum ----------------
#define BSTRD 40
#define ASZ  (256*BSTRD)
#define BSZ  (128*BSTRD)
#define STGE (ASZ+BSZ)
#define SMEM_BIG (3*STGE*2)   // 92160 B

__global__ void __launch_bounds__(256, 2) k_gemm_big(
        const __half* __restrict__ A, const __half* __restrict__ W,
        const float* __restrict__ bias,
        __half* __restrict__ out, int M, int Nstride, int K, int gelu) {
    extern __shared__ __half smem[];

    int tid = threadIdx.x, lane = tid & 31, wid = tid >> 5;
    int warp_m = wid & 3, warp_n = wid >> 2;
    int gm0 = blockIdx.y * 256;
    int gn0 = blockIdx.x * 128;

    uint32_t acch[4][8][2];
    #pragma unroll
    for (int mi = 0; mi < 4; mi++)
        #pragma unroll
        for (int nt = 0; nt < 8; nt++) { acch[mi][nt][0] = 0u; acch[mi][nt][1] = 0u; }

    uint32_t sb = smem_u32(smem);
    int lr = tid >> 2, lc = (tid & 3) * 8;

    const __half* Ag = A + (size_t)(gm0 + lr) * K + lc;
    const __half* Wg = W + (size_t)(gn0 + lr) * K + lc;
    uint32_t sa_w = sb + (lr * BSTRD + lc) * 2;
    uint32_t sb_w = sb + (ASZ + lr * BSTRD + lc) * 2;

    int nk = K >> 5;
    #pragma unroll
    for (int s = 0; s < 2; s++) {
        uint32_t so = s * STGE * 2;
        #pragma unroll
        for (int j = 0; j < 4; j++)
            cpasync16(sa_w + so + j * 64 * BSTRD * 2, Ag + s * 32 + (size_t)(j * 64) * K);
        #pragma unroll
        for (int j = 0; j < 2; j++)
            cpasync16(sb_w + so + j * 64 * BSTRD * 2, Wg + s * 32 + (size_t)(j * 64) * K);
        cpasync_commit();
    }

    int st = 0;
    for (int ch = 0; ch < nk; ch++) {
        if (ch + 1 < nk) cpasync_wait<1>(); else cpasync_wait<0>();
        __syncthreads();
        if (ch + 2 < nk) {
            int st2 = st + 2; if (st2 >= 3) st2 -= 3;
            uint32_t so = st2 * STGE * 2;
            const __half* Ag2 = Ag + (ch + 2) * 32;
            const __half* Wg2 = Wg + (ch + 2) * 32;
            #pragma unroll
            for (int j = 0; j < 4; j++)
                cpasync16(sa_w + so + j * 64 * BSTRD * 2, Ag2 + (size_t)(j * 64) * K);
            #pragma unroll
            for (int j = 0; j < 2; j++)
                cpasync16(sb_w + so + j * 64 * BSTRD * 2, Wg2 + (size_t)(j * 64) * K);
            cpasync_commit();
        }

        uint32_t aAddr = sb + (st * STGE + (warp_m * 64 + (lane & 15)) * BSTRD + (lane >> 4) * 8) * 2;
        uint32_t bAddr = sb + (st * STGE + ASZ + (warp_n * 64 + (lane & 15)) * BSTRD + (lane >> 4) * 8) * 2;
        #pragma unroll
        for (int ks = 0; ks < 2; ks++) {
            uint32_t a[4][4], b[4][4];
            #pragma unroll
            for (int mi = 0; mi < 4; mi++)
                ldsm_x4(a[mi], aAddr + (mi * 16 * BSTRD + ks * 16) * 2);
            #pragma unroll
            for (int g = 0; g < 4; g++)
                ldsm_x4(b[g], bAddr + (g * 16 * BSTRD + ks * 16) * 2);
            #pragma unroll
            for (int mi = 0; mi < 4; mi++)
                #pragma unroll
                for (int nt = 0; nt < 8; nt++)
                    mma16816h(acch[mi][nt], a[mi], b[nt >> 1][nt & 1], b[nt >> 1][2 + (nt & 1)]);
        }
        if (++st == 3) st = 0;
    }

    int row_base = gm0 + warp_m * 64 + (lane >> 2);
    int col_base = gn0 + warp_n * 64 + (lane & 3) * 2;

    #pragma unroll
    for (int mi = 0; mi < 4; mi++) {
        #pragma unroll
        for (int nt = 0; nt < 8; nt++) {
            int col = col_base + nt * 8;
            float bc0 = bias[col], bc1 = bias[col + 1];
            #pragma unroll
            for (int h = 0; h < 2; h++) {
                int r = row_base + mi * 16 + h * 8;
                __half2 hh = *reinterpret_cast<__half2*>(&acch[mi][nt][h]);
                float2 f = __half22float2(hh);
                float v0 = f.x + bc0, v1 = f.y + bc1;
                if (gelu) { v0 = gelu_exact(v0); v1 = gelu_exact(v1); }
                __half2 p = __floats2half2_rn(v0, v1);
                *reinterpret_cast<uint32_t*>(out + (size_t)r * Nstride + col) =
                    *reinterpret_cast<uint32_t*>(&p);
            }
        }
    }
}

// ---------------- TAIL GEMM: 128x64 cols [coff, coff+64), f16 accum, 3-stage ----------------
#define ASTR 40
#define BSTR 40
#define A_ST (128*ASTR)
#define B_ST (64*BSTR)

__global__ void __launch_bounds__(256, 3) k_gemm_tail(
        const __half* __restrict__ A, const __half* __restrict__ W /* pre-offset by coff*K */,
        const float* __restrict__ bias,
        __half* __restrict__ out, int M, int Nstride, int coff, int K) {
    __shared__ __half sA[3*A_ST];
    __shared__ __half sB[3*B_ST];

    int tid = threadIdx.x, lane = tid & 31, wid = tid >> 5;
    int warp_m = wid & 3, warp_n = wid >> 2;
    int gm0 = blockIdx.y * 128;

    uint32_t acch[2][4][2];
    #pragma unroll
    for (int mi = 0; mi < 2; mi++)
        #pragma unroll
        for (int ni = 0; ni < 4; ni++) { acch[mi][ni][0] = 0u; acch[mi][ni][1] = 0u; }

    uint32_t sAu = smem_u32(sA), sBu = smem_u32(sB);
    int lrA = tid >> 2, lcA = (tid & 3) * 8;

    const __half* Ag = A + (size_t)(gm0 + lrA) * K + lcA;
    const __half* Wg = W + (size_t)lrA * K + lcA;
    uint32_t sa_w = sAu + (lrA * ASTR + lcA) * 2;
    uint32_t sb_w = sBu + (lrA * BSTR + lcA) * 2;

    int nk = K >> 5;
    #pragma unroll
    for (int s = 0; s < 2; s++) {
        cpasync16(sa_w + s * A_ST * 2,             Ag + s * 32);
        cpasync16(sa_w + (s * A_ST + 64*ASTR) * 2, Ag + s * 32 + (size_t)64 * K);
        cpasync16(sb_w + s * B_ST * 2,             Wg + s * 32);
        cpasync_commit();
    }

    int st = 0;
    for (int ch = 0; ch < nk; ch++) {
        if (ch + 1 < nk) cpasync_wait<1>(); else cpasync_wait<0>();
        __syncthreads();
        if (ch + 2 < nk) {
            int st2 = st + 2; if (st2 >= 3) st2 -= 3;
            const __half* Ag2 = Ag + (ch + 2) * 32;
            const __half* Wg2 = Wg + (ch + 2) * 32;
            cpasync16(sa_w + st2 * A_ST * 2,             Ag2);
            cpasync16(sa_w + (st2 * A_ST + 64*ASTR) * 2, Ag2 + (size_t)64 * K);
            cpasync16(sb_w + st2 * B_ST * 2,             Wg2);
            cpasync_commit();
        }

        uint32_t aAddr = sAu + (st * A_ST + (warp_m * 32 + (lane & 15)) * ASTR + (lane >> 4) * 8) * 2;
        uint32_t bAddr = sBu + (st * B_ST + (warp_n * 32 + (lane & 15)) * BSTR + (lane >> 4) * 8) * 2;
        #pragma unroll
        for (int ks = 0; ks < 2; ks++) {
            uint32_t a[2][4], b[2][4];
            #pragma unroll
            for (int mi = 0; mi < 2; mi++)
                ldsm_x4(a[mi], aAddr + (mi * 16 * ASTR + ks * 16) * 2);
            #pragma unroll
            for (int nj = 0; nj < 2; nj++)
                ldsm_x4(b[nj], bAddr + (nj * 16 * BSTR + ks * 16) * 2);
            #pragma unroll
            for (int mi = 0; mi < 2; mi++)
                #pragma unroll
                for (int ni = 0; ni < 4; ni++)
                    mma16816h(acch[mi][ni], a[mi], b[ni >> 1][ni & 1], b[ni >> 1][2 + (ni & 1)]);
        }
        if (++st == 3) st = 0;
    }

    int row_base = gm0 + warp_m * 32 + (lane >> 2);
    int col_base = coff + warp_n * 32 + (lane & 3) * 2;

    #pragma unroll
    for (int mi = 0; mi < 2; mi++) {
        #pragma unroll
        for (int ni = 0; ni < 4; ni++) {
            int col = col_base + ni * 8;
            float bc0 = bias[col], bc1 = bias[col + 1];
            #pragma unroll
            for (int h = 0; h < 2; h++) {
                int r = row_base + mi * 16 + h * 8;
                __half2 hh = *reinterpret_cast<__half2*>(&acch[mi][ni][h]);
                float2 f = __half22float2(hh);
                __half2 p = __floats2half2_rn(f.x + bc0, f.y + bc1);
                *reinterpret_cast<uint32_t*>(out + (size_t)r * Nstride + col) =
                    *reinterpret_cast<uint32_t*>(&p);
            }
        }
    }
}

// ---------------- fc2 GEMM: 128x64, f32 accum, 3-stage; epilogue recomputes residual ----------------
__global__ void __launch_bounds__(256, 3) k_gemm_fc2(
        const __half* __restrict__ A, const __half* __restrict__ W,
        const float* __restrict__ bias, const float* __restrict__ x,
        float* __restrict__ out, int M, int N, int K) {
    __shared__ __half sA[3*A_ST];
    __shared__ __half sB[3*B_ST];

    int tid = threadIdx.x, lane = tid & 31, wid = tid >> 5;
    int warp_m = wid & 3, warp_n = wid >> 2;
    int gm0 = blockIdx.y * 128;
    int gn0 = blockIdx.x * 64;

    float accf[2][4][4];
    #pragma unroll
    for (int mi = 0; mi < 2; mi++)
        #pragma unroll
        for (int ni = 0; ni < 4; ni++)
            #pragma unroll
            for (int q = 0; q < 4; q++) accf[mi][ni][q] = 0.f;

    uint32_t sAu = smem_u32(sA), sBu = smem_u32(sB);
    int lrA = tid >> 2, lcA = (tid & 3) * 8;

    const __half* Ag = A + (size_t)(gm0 + lrA) * K + lcA;
    const __half* Wg = W + (size_t)(gn0 + lrA) * K + lcA;
    uint32_t sa_w = sAu + (lrA * ASTR + lcA) * 2;
    uint32_t sb_w = sBu + (lrA * BSTR + lcA) * 2;

    int nk = K >> 5;
    #pragma unroll
    for (int s = 0; s < 2; s++) {
        cpasync16(sa_w + s * A_ST * 2,             Ag + s * 32);
        cpasync16(sa_w + (s * A_ST + 64*ASTR) * 2, Ag + s * 32 + (size_t)64 * K);
        cpasync16(sb_w + s * B_ST * 2,             Wg + s * 32);
        cpasync_commit();
    }

    int st = 0;
    for (int ch = 0; ch < nk; ch++) {
        if (ch + 1 < nk) cpasync_wait<1>(); else cpasync_wait<0>();
        __syncthreads();
        if (ch + 2 < nk) {
            int st2 = st + 2; if (st2 >= 3) st2 -= 3;
            const __half* Ag2 = Ag + (ch + 2) * 32;
            const __half* Wg2 = Wg + (ch + 2) * 32;
            cpasync16(sa_w + st2 * A_ST * 2,             Ag2);
            cpasync16(sa_w + (st2 * A_ST + 64*ASTR) * 2, Ag2 + (size_t)64 * K);
            cpasync16(sb_w + st2 * B_ST * 2,             Wg2);
            cpasync_commit();
        }

        uint32_t aAddr = sAu + (st * A_ST + (warp_m * 32 + (lane & 15)) * ASTR + (lane >> 4) * 8) * 2;
        uint32_t bAddr = sBu + (st * B_ST + (warp_n * 32 + (lane & 15)) * BSTR + (lane >> 4) * 8) * 2;
        #pragma unroll
        for (int ks = 0; ks < 2; ks++) {
            uint32_t a[2][4], b[2][4];
            #pragma unroll
            for (int mi = 0; mi < 2; mi++)
                ldsm_x4(a[mi], aAddr + (mi * 16 * ASTR + ks * 16) * 2);
            #pragma unroll
            for (int nj = 0; nj < 2; nj++)
                ldsm_x4(b[nj], bAddr + (nj * 16 * BSTR + ks * 16) * 2);
            #pragma unroll
            for (int mi = 0; mi < 2; mi++)
                #pragma unroll
                for (int ni = 0; ni < 4; ni++)
                    mma16816f(accf[mi][ni], a[mi], b[ni >> 1][ni & 1], b[ni >> 1][2 + (ni & 1)]);
        }
        if (++st == 3) st = 0;
    }

    int row_base = gm0 + warp_m * 32 + (lane >> 2);
    int col_base = gn0 + warp_n * 32 + (lane & 3) * 2;

    size_t pbase[2][2];
    #pragma unroll
    for (int mi = 0; mi < 2; mi++)
        #pragma unroll
        for (int h = 0; h < 2; h++) {
            int r = row_base + mi * 16 + h * 8;
            int img = r / (HH*WW);
            int hw  = r % (HH*WW);
            int hh = hw / WW, ww = hw % WW;
            int hs = (hh + HH - SHIFT) % HH;
            int ws = (ww + WW - SHIFT) % WW;
            int win = (hs / WSZ) * 8 + (ws / WSZ);
            int t   = (hs % WSZ) * WSZ + (ws % WSZ);
            pbase[mi][h] = ((size_t)(img * NWIN_I + win) * TOK + t) * CC;
        }

    #pragma unroll
    for (int mi = 0; mi < 2; mi++) {
        #pragma unroll
        for (int ni = 0; ni < 4; ni++) {
            int col = col_base + ni * 8;
            float bc0 = bias[col], bc1 = bias[col + 1];
            #pragma unroll
            for (int h = 0; h < 2; h++) {
                int r = row_base + mi * 16 + h * 8;
                float v0 = accf[mi][ni][h * 2 + 0] + bc0;
                float v1 = accf[mi][ni][h * 2 + 1] + bc1;
                const float2 xv = *reinterpret_cast<const float2*>(x + (size_t)r * N + col);
                float2 pv = __half22float2(
                    *reinterpret_cast<const __half2*>(g_proj + pbase[mi][h] + col));
                float2 o;
                o.x = v0 + xv.x + pv.x;
                o.y = v1 + xv.y + pv.y;
                *reinterpret_cast<float2*>(out + (size_t)r * N + col) = o;
            }
        }
    }
}

// ---------------- tensor-core windowed attention (f16 in, f32 accum) ----------------
#define QSTR 40
#define VSTR 72

__global__ void __launch_bounds__(128) k_attn_tc() {
    int blk = blockIdx.x;
    int n = blk / NHEADS, head = blk % NHEADS;
    int win = n % NWIN_I;

    __shared__ __half sQ[64 * QSTR];
    __shared__ __half sK[64 * QSTR];
    __shared__ __half sVt[32 * VSTR];

    int tid = threadIdx.x, lane = tid & 31, warp = tid >> 5;
    const float scale = 0.17677669529663687f;

    {
        for (int i = tid; i < 600; i += 128) {
            int r = 49 + i / 40, c = i % 40;
            sQ[r * QSTR + c] = __ushort_as_half(0);
            sK[r * QSTR + c] = __ushort_as_half(0);
        }
        for (int i = tid; i < 480; i += 128) {
            int r = i / 15, c = 49 + i % 15;
            sVt[r * VSTR + c] = __ushort_as_half(0);
        }
    }

    const __half* base = g_qkv + (size_t)n * TOK * (3*CC) + head * HD;
    for (int i = tid; i < TOK * 16; i += 128) {
        int t = i >> 4, d2 = (i & 15) * 2;
        const __half* p = base + t * (3*CC) + d2;
        float2 q2 = __half22float2(*reinterpret_cast<const __half2*>(p));
        __half2 qs = __floats2half2_rn(q2.x * scale, q2.y * scale);
        *reinterpret_cast<uint32_t*>(sQ + t * QSTR + d2) = *reinterpret_cast<uint32_t*>(&qs);
        *reinterpret_cast<uint32_t*>(sK + t * QSTR + d2) =
            *reinterpret_cast<const uint32_t*>(p + CC);
        __half2 v2 = *reinterpret_cast<const __half2*>(p + 2*CC);
        sVt[d2 * VSTR + t]       = __low2half(v2);
        sVt[(d2 + 1) * VSTR + t] = __high2half(v2);
    }
    __syncthreads();

    uint32_t sQu = smem_u32(sQ), sKu = smem_u32(sK), sVu = smem_u32(sVt);

    float sacc[8][4];
    #pragma unroll
    for (int j = 0; j < 8; j++)
        #pragma unroll
        for (int q = 0; q < 4; q++) sacc[j][q] = 0.f;

    uint32_t qAddr = sQu + ((warp * 16 + (lane & 15)) * QSTR + (lane >> 4) * 8) * 2;
    #pragma unroll
    for (int kc = 0; kc < 2; kc++) {
        uint32_t aq[4];
        ldsm_x4(aq, qAddr + kc * 32);
        #pragma unroll
        for (int jj = 0; jj < 4; jj++) {
            uint32_t bk[4];
            ldsm_x4(bk, sKu + ((jj * 16 + (lane & 15)) * QSTR + (lane >> 4) * 8 + kc * 16) * 2);
            mma16816f(sacc[jj*2 + 0], aq, bk[0], bk[2]);
            mma16816f(sacc[jj*2 + 1], aq, bk[1], bk[3]);
        }
    }

    int g = lane >> 2, qq = lane & 3;
    int r0 = warp * 16 + g, r1 = r0 + 8;
    const __half* bmrow = g_bm + (size_t)(win * NHEADS + head) * (TOK*BMS);

    float m0 = -1e30f, m1 = -1e30f;
    #pragma unroll
    for (int j = 0; j < 8; j++) {
        int t0 = j * 8 + qq * 2;
        float b00, b01, b10, b11;
        if (t0 < TOK) {
            if (r0 < TOK) {
                float2 f = __half22float2(*reinterpret_cast<const __half2*>(bmrow + r0*BMS + t0));
                b00 = f.x; b01 = f.y;
            } else { b00 = 0.f; b01 = 0.f; }
            if (r1 < TOK) {
                float2 f = __half22float2(*reinterpret_cast<const __half2*>(bmrow + r1*BMS + t0));
                b10 = f.x; b11 = f.y;
            } else { b10 = 0.f; b11 = 0.f; }
        } else {
            b00 = b01 = b10 = b11 = -1e30f;
        }
        sacc[j][0] += b00; sacc[j][1] += b01;
        sacc[j][2] += b10; sacc[j][3] += b11;
        m0 = fmaxf(m0, fmaxf(sacc[j][0], sacc[j][1]));
        m1 = fmaxf(m1, fmaxf(sacc[j][2], sacc[j][3]));
    }
    m0 = fmaxf(m0, __shfl_xor_sync(0xffffffffu, m0, 1));
    m0 = fmaxf(m0, __shfl_xor_sync(0xffffffffu, m0, 2));
    m1 = fmaxf(m1, __shfl_xor_sync(0xffffffffu, m1, 1));
    m1 = fmaxf(m1, __shfl_xor_sync(0xffffffffu, m1, 2));

    float sum0 = 0.f, sum1 = 0.f;
    #pragma unroll
    for (int j = 0; j < 8; j++) {
        sacc[j][0] = __expf(sacc[j][0] - m0);
        sacc[j][1] = __expf(sacc[j][1] - m0);
        sacc[j][2] = __expf(sacc[j][2] - m1);
        sacc[j][3] = __expf(sacc[j][3] - m1);
        sum0 += sacc[j][0] + sacc[j][1];
        sum1 += sacc[j][2] + sacc[j][3];
    }
    sum0 += __shfl_xor_sync(0xffffffffu, sum0, 1);
    sum0 += __shfl_xor_sync(0xffffffffu, sum0, 2);
    sum1 += __shfl_xor_sync(0xffffffffu, sum1, 1);
    sum1 += __shfl_xor_sync(0xffffffffu, sum1, 2);
    float inv0 = 1.0f / sum0, inv1 = 1.0f / sum1;

    uint32_t pr0[8], pr1[8];
    #pragma unroll
    for (int j = 0; j < 8; j++) {
        __half2 p0 = __floats2half2_rn(sacc[j][0] * inv0, sacc[j][1] * inv0);
        __half2 p1 = __floats2half2_rn(sacc[j][2] * inv1, sacc[j][3] * inv1);
        pr0[j] = *reinterpret_cast<uint32_t*>(&p0);
        pr1[j] = *reinterpret_cast<uint32_t*>(&p1);
    }

    float oacc[4][4];
    #pragma unroll
    for (int nt = 0; nt < 4; nt++)
        #pragma unroll
        for (int q = 0; q < 4; q++) oacc[nt][q] = 0.f;

    #pragma unroll
    for (int kk = 0; kk < 4; kk++) {
        uint32_t aP[4] = { pr0[2*kk], pr1[2*kk], pr0[2*kk+1], pr1[2*kk+1] };
        #pragma unroll
        for (int nn = 0; nn < 2; nn++) {
            uint32_t bv[4];
            ldsm_x4(bv, sVu + ((nn * 16 + (lane & 15)) * VSTR + (lane >> 4) * 8 + kk * 16) * 2);
            mma16816f(oacc[nn*2 + 0], aP, bv[0], bv[2]);
            mma16816f(oacc[nn*2 + 1], aP, bv[1], bv[3]);
        }
    }

    __half* outb = g_att + (size_t)n * TOK * CC + head * HD;
    #pragma unroll
    for (int nt = 0; nt < 4; nt++) {
        int col = nt * 8 + qq * 2;
        if (r0 < TOK) {
            __half2 o = __floats2half2_rn(oacc[nt][0], oacc[nt][1]);
            *reinterpret_cast<uint32_t*>(outb + (size_t)r0 * CC + col) =
                *reinterpret_cast<uint32_t*>(&o);
        }
        if (r1 < TOK) {
            __half2 o = __floats2half2_rn(oacc[nt][2], oacc[nt][3]);
            *reinterpret_cast<uint32_t*>(outb + (size_t)r1 * CC + col) =
                *reinterpret_cast<uint32_t*>(&o);
        }
    }
}

// ---------------- launch ----------------
extern "C" void kernel_launch(void* const* d_in, const int* in_sizes, int n_in,
                              void* d_out, int out_size) {
    const float* x       = (const float*)d_in[0];
    const float* norm1_g = (const float*)d_in[1];
    const float* norm1_b = (const float*)d_in[2];
    const float* qkv_w   = (const float*)d_in[3];
    const float* qkv_b   = (const float*)d_in[4];
    const float* rpb     = (const float*)d_in[5];
    const float* proj_w  = (const float*)d_in[6];
    const float* proj_b  = (const float*)d_in[7];
    const float* norm2_g = (const float*)d_in[8];
    const float* norm2_b = (const float*)d_in[9];
    const float* fc1_w   = (const float*)d_in[10];
    const float* fc1_b   = (const float*)d_in[11];
    const float* fc2_w   = (const float*)d_in[12];
    const float* fc2_b   = (const float*)d_in[13];
    const int*   relidx;
    const float* amask;
    if (in_sizes[14] == TOK * TOK) {
        relidx = (const int*)d_in[14];  amask = (const float*)d_in[15];
    } else {
        relidx = (const int*)d_in[15];  amask = (const float*)d_in[14];
    }
    float* out = (float*)d_out;

    __half *p_xw, *p_qkv, *p_att, *p_proj, *p_ln2, *p_hid;
    __half *p_wqkv, *p_wproj, *p_wfc1, *p_wfc2;
    cudaGetSymbolAddress((void**)&p_xw,    g_xw);
    cudaGetSymbolAddress((void**)&p_qkv,   g_qkv);
    cudaGetSymbolAddress((void**)&p_att,   g_att);
    cudaGetSymbolAddress((void**)&p_proj,  g_proj);
    cudaGetSymbolAddress((void**)&p_ln2,   g_ln2);
    cudaGetSymbolAddress((void**)&p_hid,   g_hid);
    cudaGetSymbolAddress((void**)&p_wqkv,  g_wqkv);
    cudaGetSymbolAddress((void**)&p_wproj, g_wproj);
    cudaGetSymbolAddress((void**)&p_wfc1,  g_wfc1);
    cudaGetSymbolAddress((void**)&p_wfc2,  g_wfc2);

    cudaFuncSetAttribute(k_gemm_big, cudaFuncAttributeMaxDynamicSharedMemorySize, SMEM_BIG);

    k_f2h_all<<<(NW_ALL + 255)/256, 256>>>(qkv_w, proj_w, fc1_w, fc2_w);
    k_bias<<<NWIN_I*NHEADS, 256>>>(rpb, relidx, amask);

    k_ln1_shift_part<<<NTOK/8, 256>>>(x, norm1_g, norm1_b);

    // qkv: 4 big tiles (cols 0..511) + tail (cols 512..575); no padded compute
    {
        dim3 grid(4, NTOK/256);
        k_gemm_big<<<grid, 256, SMEM_BIG>>>(p_xw, p_wqkv, qkv_b, p_qkv, NTOK, 3*CC, CC, 0);
        dim3 gt(1, NTOK/128);
        k_gemm_tail<<<gt, 256>>>(p_xw, p_wqkv + (size_t)512*CC, qkv_b, p_qkv, NTOK, 3*CC, 512, CC);
    }

    k_attn_tc<<<NWIN * NHEADS, 128>>>();

    // proj: 1 big tile (cols 0..127) + tail (cols 128..191)
    {
        dim3 grid(1, NTOK/256);
        k_gemm_big<<<grid, 256, SMEM_BIG>>>(p_att, p_wproj, proj_b, p_proj, NTOK, CC, CC, 0);
        dim3 gt(1, NTOK/128);
        k_gemm_tail<<<gt, 256>>>(p_att, p_wproj + (size_t)128*CC, proj_b, p_proj, NTOK, CC, 128, CC);
    }

    // LN2 only (no x1 materialization)
    k_ln2<<<NTOK/8, 256>>>(x, norm2_g, norm2_b);

    // fc1 + GELU: N=768 exact (6 tiles)
    {
        dim3 grid(HIDDEN/128, NTOK/256);
        k_gemm_big<<<grid, 256, SMEM_BIG>>>(p_ln2, p_wfc1, fc1_b, p_hid, NTOK, HIDDEN, CC, 1);
    }

    // fc2 + recomputed residual -> out (f32 accum, K=768)
    {
        dim3 grid(CC/64, NTOK/128);
        k_gemm_fc2<<<grid, 256>>>(p_hid, p_wfc2, fc2_b, x, out, NTOK, CC, HIDDEN);
    }
}

// round 16
// speedup vs baseline: 1.0196x; 1.0196x over previous
#include <cuda_runtime.h>
#include <cuda_fp16.h>
#include <math.h>
#include <stdint.h>

// ---------------- problem constants ----------------
#define BB     64
#define HH     56
#define WW     56
#define CC     192
#define NHEADS 6
#define HD     32
#define WSZ    7
#define TOK    49
#define BMS    50          // padded bias-table row stride
#define NWIN_I 64
#define SHIFT  3
#define NTOK   (BB*HH*WW)   // 200704
#define NWIN   (BB*NWIN_I)  // 4096
#define HIDDEN 768

// ---------------- scratch (device globals; zero-initialized, no allocs allowed) ----------------
__device__ __half g_xw  [(size_t)NTOK*CC];
__device__ __half g_qkv [(size_t)NTOK*3*CC];
__device__ __half g_att [(size_t)NTOK*CC];
__device__ __half g_proj[(size_t)NTOK*CC];
__device__ __half g_ln2 [(size_t)NTOK*CC];
__device__ __half g_hid [(size_t)NTOK*HIDDEN];
__device__ __half g_wqkv [640*CC];     // 576 real rows, padded to 640 (zero-init)
__device__ __half g_wproj[256*CC];     // 192 real rows, padded to 256
__device__ __half g_wfc1 [HIDDEN*CC];  // 768 rows exact
__device__ __half g_wfc2 [CC*HIDDEN];
__device__ __half g_bm  [NWIN_I*NHEADS*TOK*BMS];   // bias+mask table, f16, padded rows

// ---------------- helpers ----------------
__device__ __forceinline__ uint32_t smem_u32(const void* p) {
    uint32_t a;
    asm("{ .reg .u64 t; cvta.to.shared.u64 t, %1; cvt.u32.u64 %0, t; }" : "=r"(a) : "l"(p));
    return a;
}
__device__ __forceinline__ float gelu_exact(float x) {
    return 0.5f * x * (1.0f + erff(x * 0.70710678118654752f));
}
__device__ __forceinline__ void ldsm_x4(uint32_t* r, uint32_t addr) {
    asm volatile("ldmatrix.sync.aligned.m8n8.x4.shared.b16 {%0,%1,%2,%3}, [%4];"
                 : "=r"(r[0]), "=r"(r[1]), "=r"(r[2]), "=r"(r[3]) : "r"(addr));
}
__device__ __forceinline__ void mma16816f(float* d, const uint32_t* a, uint32_t b0, uint32_t b1) {
    asm volatile(
        "mma.sync.aligned.m16n8k16.row.col.f32.f16.f16.f32 "
        "{%0,%1,%2,%3}, {%4,%5,%6,%7}, {%8,%9}, {%0,%1,%2,%3};"
        : "+f"(d[0]), "+f"(d[1]), "+f"(d[2]), "+f"(d[3])
        : "r"(a[0]), "r"(a[1]), "r"(a[2]), "r"(a[3]), "r"(b0), "r"(b1));
}
__device__ __forceinline__ void mma16816h(uint32_t* d, const uint32_t* a, uint32_t b0, uint32_t b1) {
    asm volatile(
        "mma.sync.aligned.m16n8k16.row.col.f16.f16.f16.f16 "
        "{%0,%1}, {%2,%3,%4,%5}, {%6,%7}, {%0,%1};"
        : "+r"(d[0]), "+r"(d[1])
        : "r"(a[0]), "r"(a[1]), "r"(a[2]), "r"(a[3]), "r"(b0), "r"(b1));
}
__device__ __forceinline__ void cpasync16(uint32_t smem, const void* gptr) {
    asm volatile("cp.async.cg.shared.global [%0], [%1], 16;" :: "r"(smem), "l"(gptr));
}
__device__ __forceinline__ void cpasync_commit() {
    asm volatile("cp.async.commit_group;" ::: "memory");
}
template<int N> __device__ __forceinline__ void cpasync_wait() {
    asm volatile("cp.async.wait_group %0;" :: "n"(N) : "memory");
}

// ---------------- fused prologue: LN1(+shift+partition) | weights f32->f16 | bias table ----------------
#define NW_QKV (3*CC*CC)
#define NW_PRJ (CC*CC)
#define NW_FC1 (HIDDEN*CC)
#define NW_FC2 (CC*HIDDEN)
#define NW_ALL (NW_QKV+NW_PRJ+NW_FC1+NW_FC2)
#define LN1_BLKS (NTOK/8)                       // 25088
#define F2H_BLKS ((NW_ALL + 255)/256)           // 2166
#define BIAS_BLKS (NWIN_I*NHEADS)               // 384
#define PRE_BLKS (LN1_BLKS + F2H_BLKS + BIAS_BLKS)

__global__ void __launch_bounds__(256) k_pre(
        const float* __restrict__ x,
        const float* __restrict__ g, const float* __restrict__ b,
        const float* __restrict__ qkv_w, const float* __restrict__ proj_w,
        const float* __restrict__ fc1_w, const float* __restrict__ fc2_w,
        const float* __restrict__ rpb, const int* __restrict__ relidx,
        const float* __restrict__ amask) {
    int bid = blockIdx.x;
    if (bid < LN1_BLKS) {
        // ---- LN1 + roll + window partition: warp-per-token, half2 stores ----
        int lane = threadIdx.x & 31, warp = threadIdx.x >> 5;
        int w = bid * 8 + warp;
        int n = w / TOK, t = w % TOK;
        int img = n / NWIN_I, win = n % NWIN_I;
        int hs = (win / 8) * WSZ + t / WSZ;
        int ws = (win % 8) * WSZ + t % WSZ;
        int hsrc = (hs + SHIFT) % HH;
        int wsrc = (ws + SHIFT) % WW;
        const float* row = x + ((size_t)img * (HH*WW) + hsrc * WW + wsrc) * CC;

        float2 v[3];
        float s = 0.f, s2 = 0.f;
        #pragma unroll
        for (int j = 0; j < 3; j++) {
            v[j] = *reinterpret_cast<const float2*>(row + lane*2 + 64*j);
            s += v[j].x + v[j].y;
            s2 += v[j].x*v[j].x + v[j].y*v[j].y;
        }
        #pragma unroll
        for (int o = 16; o > 0; o >>= 1) {
            s  += __shfl_xor_sync(0xffffffffu, s,  o);
            s2 += __shfl_xor_sync(0xffffffffu, s2, o);
        }
        float mean = s * (1.0f / CC);
        float var  = s2 * (1.0f / CC) - mean * mean;
        float inv  = rsqrtf(var + 1e-5f);
        __half* outp = g_xw + (size_t)w * CC;
        #pragma unroll
        for (int j = 0; j < 3; j++) {
            int c = lane*2 + 64*j;
            __half2 o = __floats2half2_rn((v[j].x - mean) * inv * g[c]   + b[c],
                                          (v[j].y - mean) * inv * g[c+1] + b[c+1]);
            *reinterpret_cast<uint32_t*>(outp + c) = *reinterpret_cast<uint32_t*>(&o);
        }
        return;
    }
    bid -= LN1_BLKS;
    if (bid < F2H_BLKS) {
        // ---- weights f32 -> f16 ----
        int i = bid * 256 + threadIdx.x;
        if (i < NW_QKV) { g_wqkv[i] = __float2half(qkv_w[i]); return; }
        i -= NW_QKV;
        if (i < NW_PRJ) { g_wproj[i] = __float2half(proj_w[i]); return; }
        i -= NW_PRJ;
        if (i < NW_FC1) { g_wfc1[i] = __float2half(fc1_w[i]); return; }
        i -= NW_FC1;
        if (i < NW_FC2) { g_wfc2[i] = __float2half(fc2_w[i]); }
        return;
    }
    bid -= F2H_BLKS;
    {
        // ---- bias+mask table (f16, padded rows; pad cols = -30000) ----
        int win = bid / NHEADS, h = bid % NHEADS;
        for (int i = threadIdx.x; i < TOK*BMS; i += 256) {
            int r = i / BMS, t = i % BMS;
            float v = (t < TOK)
                ? rpb[relidx[r*TOK + t] * NHEADS + h] + amask[win * (TOK*TOK) + r*TOK + t]
                : -30000.0f;
            g_bm[(size_t)bid * (TOK*BMS) + i] = __float2half(v);
        }
    }
}

// ---------------- window reverse + roll + residual + LN2 (LN output ONLY) ----------------
__global__ void __launch_bounds__(256) k_ln2(const float* __restrict__ x,
                            const float* __restrict__ g,
                            const float* __restrict__ b) {
    int lane = threadIdx.x & 31, warp = threadIdx.x >> 5;
    int tok = blockIdx.x * 8 + warp;
    int img = tok / (HH*WW);
    int hw  = tok % (HH*WW);
    int hh = hw / WW, ww = hw % WW;
    int hs = (hh + HH - SHIFT) % HH;
    int ws = (ww + WW - SHIFT) % WW;
    int win = (hs / WSZ) * 8 + (ws / WSZ);
    int t   = (hs % WSZ) * WSZ + (ws % WSZ);
    const __half* prow = g_proj + ((size_t)(img * NWIN_I + win) * TOK + t) * CC;
    const float* xrow = x + (size_t)tok * CC;

    float2 v[3];
    float s = 0.f, s2 = 0.f;
    #pragma unroll
    for (int j = 0; j < 3; j++) {
        int c = lane*2 + 64*j;
        float2 xv = *reinterpret_cast<const float2*>(xrow + c);
        float2 pv = __half22float2(*reinterpret_cast<const __half2*>(prow + c));
        v[j].x = xv.x + pv.x;
        v[j].y = xv.y + pv.y;
        s += v[j].x + v[j].y;
        s2 += v[j].x*v[j].x + v[j].y*v[j].y;
    }
    #pragma unroll
    for (int o = 16; o > 0; o >>= 1) {
        s  += __shfl_xor_sync(0xffffffffu, s,  o);
        s2 += __shfl_xor_sync(0xffffffffu, s2, o);
    }
    float mean = s * (1.0f / CC);
    float var  = s2 * (1.0f / CC) - mean * mean;
    float inv  = rsqrtf(var + 1e-5f);
    __half* outp = g_ln2 + (size_t)tok * CC;
    #pragma unroll
    for (int j = 0; j < 3; j++) {
        int c = lane*2 + 64*j;
        __half2 o = __floats2half2_rn((v[j].x - mean) * inv * g[c]   + b[c],
                                      (v[j].y - mean) * inv * g[c+1] + b[c+1]);
        *reinterpret_cast<uint32_t*>(outp + c) = *reinterpret_cast<uint32_t*>(&o);
    }
}

// ---------------- BIG-TILE GEMM: BM=256, BN=128, warp tile 64x64, f16 accum ----------------
#define BSTRD 40
#define ASZ  (256*BSTRD)
#define BSZ  (128*BSTRD)
#define STGE (ASZ+BSZ)
#define SMEM_BIG (3*STGE*2)   // 92160 B

__global__ void __launch_bounds__(256, 2) k_gemm_big(
        const __half* __restrict__ A, const __half* __restrict__ W,
        const float* __restrict__ bias,
        __half* __restrict__ out, int M, int Nreal, int K, int gelu) {
    extern __shared__ __half smem[];

    int tid = threadIdx.x, lane = tid & 31, wid = tid >> 5;
    int warp_m = wid & 3, warp_n = wid >> 2;
    int gm0 = blockIdx.y * 256;
    int gn0 = blockIdx.x * 128;

    uint32_t acch[4][8][2];
    #pragma unroll
    for (int mi = 0; mi < 4; mi++)
        #pragma unroll
        for (int nt = 0; nt < 8; nt++) { acch[mi][nt][0] = 0u; acch[mi][nt][1] = 0u; }

    uint32_t sb = smem_u32(smem);
    int lr = tid >> 2, lc = (tid & 3) * 8;

    const __half* Ag = A + (size_t)(gm0 + lr) * K + lc;
    const __half* Wg = W + (size_t)(gn0 + lr) * K + lc;
    uint32_t sa_w = sb + (lr * BSTRD + lc) * 2;
    uint32_t sb_w = sb + (ASZ + lr * BSTRD + lc) * 2;

    int nk = K >> 5;
    #pragma unroll
    for (int s = 0; s < 2; s++) {
        uint32_t so = s * STGE * 2;
        #pragma unroll
        for (int j = 0; j < 4; j++)
            cpasync16(sa_w + so + j * 64 * BSTRD * 2, Ag + s * 32 + (size_t)(j * 64) * K);
        #pragma unroll
        for (int j = 0; j < 2; j++)
            cpasync16(sb_w + so + j * 64 * BSTRD * 2, Wg + s * 32 + (size_t)(j * 64) * K);
        cpasync_commit();
    }

    int st = 0;
    for (int ch = 0; ch < nk; ch++) {
        if (ch + 1 < nk) cpasync_wait<1>(); else cpasync_wait<0>();
        __syncthreads();
        if (ch + 2 < nk) {
            int st2 = st + 2; if (st2 >= 3) st2 -= 3;
            uint32_t so = st2 * STGE * 2;
            const __half* Ag2 = Ag + (ch + 2) * 32;
            const __half* Wg2 = Wg + (ch + 2) * 32;
            #pragma unroll
            for (int j = 0; j < 4; j++)
                cpasync16(sa_w + so + j * 64 * BSTRD * 2, Ag2 + (size_t)(j * 64) * K);
            #pragma unroll
            for (int j = 0; j < 2; j++)
                cpasync16(sb_w + so + j * 64 * BSTRD * 2, Wg2 + (size_t)(j * 64) * K);
            cpasync_commit();
        }

        uint32_t aAddr = sb + (st * STGE + (warp_m * 64 + (lane & 15)) * BSTRD + (lane >> 4) * 8) * 2;
        uint32_t bAddr = sb + (st * STGE + ASZ + (warp_n * 64 + (lane & 15)) * BSTRD + (lane >> 4) * 8) * 2;
        #pragma unroll
        for (int ks = 0; ks < 2; ks++) {
            uint32_t a[4][4], b[4][4];
            #pragma unroll
            for (int mi = 0; mi < 4; mi++)
                ldsm_x4(a[mi], aAddr + (mi * 16 * BSTRD + ks * 16) * 2);
            #pragma unroll
            for (int g = 0; g < 4; g++)
                ldsm_x4(b[g], bAddr + (g * 16 * BSTRD + ks * 16) * 2);
            #pragma unroll
            for (int mi = 0; mi < 4; mi++)
                #pragma unroll
                for (int nt = 0; nt < 8; nt++)
                    mma16816h(acch[mi][nt], a[mi], b[nt >> 1][nt & 1], b[nt >> 1][2 + (nt & 1)]);
        }
        if (++st == 3) st = 0;
    }

    int row_base = gm0 + warp_m * 64 + (lane >> 2);
    int col_base = gn0 + warp_n * 64 + (lane & 3) * 2;

    #pragma unroll
    for (int mi = 0; mi < 4; mi++) {
        #pragma unroll
        for (int nt = 0; nt < 8; nt++) {
            int col = col_base + nt * 8;
            if (col >= Nreal) continue;
            float bc0 = bias[col], bc1 = bias[col + 1];
            #pragma unroll
            for (int h = 0; h < 2; h++) {
                int r = row_base + mi * 16 + h * 8;
                __half2 hh = *reinterpret_cast<__half2*>(&acch[mi][nt][h]);
                float2 f = __half22float2(hh);
                float v0 = f.x + bc0, v1 = f.y + bc1;
                if (gelu) { v0 = gelu_exact(v0); v1 = gelu_exact(v1); }
                __half2 p = __floats2half2_rn(v0, v1);
                *reinterpret_cast<uint32_t*>(out + (size_t)r * Nreal + col) =
                    *reinterpret_cast<uint32_t*>(&p);
            }
        }
    }
}

// ---------------- fc2 GEMM: 128x64, f32 accum, 3-stage; epilogue recomputes residual ----------------
#define ASTR 40
#define BSTR 40
#define A_ST (128*ASTR)
#define B_ST (64*BSTR)

__global__ void __launch_bounds__(256, 3) k_gemm_fc2(
        const __half* __restrict__ A, const __half* __restrict__ W,
        const float* __restrict__ bias, const float* __restrict__ x,
        float* __restrict__ out, int M, int N, int K) {
    __shared__ __half sA[3*A_ST];
    __shared__ __half sB[3*B_ST];

    int tid = threadIdx.x, lane = tid & 31, wid = tid >> 5;
    int warp_m = wid & 3, warp_n = wid >> 2;
    int gm0 = blockIdx.y * 128;
    int gn0 = blockIdx.x * 64;

    float accf[2][4][4];
    #pragma unroll
    for (int mi = 0; mi < 2; mi++)
        #pragma unroll
        for (int ni = 0; ni < 4; ni++)
            #pragma unroll
            for (int q = 0; q < 4; q++) accf[mi][ni][q] = 0.f;

    uint32_t sAu = smem_u32(sA), sBu = smem_u32(sB);
    int lrA = tid >> 2, lcA = (tid & 3) * 8;

    const __half* Ag = A + (size_t)(gm0 + lrA) * K + lcA;
    const __half* Wg = W + (size_t)(gn0 + lrA) * K + lcA;
    uint32_t sa_w = sAu + (lrA * ASTR + lcA) * 2;
    uint32_t sb_w = sBu + (lrA * BSTR + lcA) * 2;

    int nk = K >> 5;
    #pragma unroll
    for (int s = 0; s < 2; s++) {
        cpasync16(sa_w + s * A_ST * 2,             Ag + s * 32);
        cpasync16(sa_w + (s * A_ST + 64*ASTR) * 2, Ag + s * 32 + (size_t)64 * K);
        cpasync16(sb_w + s * B_ST * 2,             Wg + s * 32);
        cpasync_commit();
    }

    int st = 0;
    for (int ch = 0; ch < nk; ch++) {
        if (ch + 1 < nk) cpasync_wait<1>(); else cpasync_wait<0>();
        __syncthreads();
        if (ch + 2 < nk) {
            int st2 = st + 2; if (st2 >= 3) st2 -= 3;
            const __half* Ag2 = Ag + (ch + 2) * 32;
            const __half* Wg2 = Wg + (ch + 2) * 32;
            cpasync16(sa_w + st2 * A_ST * 2,             Ag2);
            cpasync16(sa_w + (st2 * A_ST + 64*ASTR) * 2, Ag2 + (size_t)64 * K);
            cpasync16(sb_w + st2 * B_ST * 2,             Wg2);
            cpasync_commit();
        }

        uint32_t aAddr = sAu + (st * A_ST + (warp_m * 32 + (lane & 15)) * ASTR + (lane >> 4) * 8) * 2;
        uint32_t bAddr = sBu + (st * B_ST + (warp_n * 32 + (lane & 15)) * BSTR + (lane >> 4) * 8) * 2;
        #pragma unroll
        for (int ks = 0; ks < 2; ks++) {
            uint32_t a[2][4], b[2][4];
            #pragma unroll
            for (int mi = 0; mi < 2; mi++)
                ldsm_x4(a[mi], aAddr + (mi * 16 * ASTR + ks * 16) * 2);
            #pragma unroll
            for (int nj = 0; nj < 2; nj++)
                ldsm_x4(b[nj], bAddr + (nj * 16 * BSTR + ks * 16) * 2);
            #pragma unroll
            for (int mi = 0; mi < 2; mi++)
                #pragma unroll
                for (int ni = 0; ni < 4; ni++)
                    mma16816f(accf[mi][ni], a[mi], b[ni >> 1][ni & 1], b[ni >> 1][2 + (ni & 1)]);
        }
        if (++st == 3) st = 0;
    }

    int row_base = gm0 + warp_m * 32 + (lane >> 2);
    int col_base = gn0 + warp_n * 32 + (lane & 3) * 2;

    size_t pbase[2][2];
    #pragma unroll
    for (int mi = 0; mi < 2; mi++)
        #pragma unroll
        for (int h = 0; h < 2; h++) {
            int r = row_base + mi * 16 + h * 8;
            int img = r / (HH*WW);
            int hw  = r % (HH*WW);
            int hh = hw / WW, ww = hw % WW;
            int hs = (hh + HH - SHIFT) % HH;
            int ws = (ww + WW - SHIFT) % WW;
            int win = (hs / WSZ) * 8 + (ws / WSZ);
            int t   = (hs % WSZ) * WSZ + (ws % WSZ);
            pbase[mi][h] = ((size_t)(img * NWIN_I + win) * TOK + t) * CC;
        }

    #pragma unroll
    for (int mi = 0; mi < 2; mi++) {
        #pragma unroll
        for (int ni = 0; ni < 4; ni++) {
            int col = col_base + ni * 8;
            float bc0 = bias[col], bc1 = bias[col + 1];
            #pragma unroll
            for (int h = 0; h < 2; h++) {
                int r = row_base + mi * 16 + h * 8;
                float v0 = accf[mi][ni][h * 2 + 0] + bc0;
                float v1 = accf[mi][ni][h * 2 + 1] + bc1;
                const float2 xv = *reinterpret_cast<const float2*>(x + (size_t)r * N + col);
                float2 pv = __half22float2(
                    *reinterpret_cast<const __half2*>(g_proj + pbase[mi][h] + col));
                float2 o;
                o.x = v0 + xv.x + pv.x;
                o.y = v1 + xv.y + pv.y;
                *reinterpret_cast<float2*>(out + (size_t)r * N + col) = o;
            }
        }
    }
}

// ---------------- tensor-core windowed attention (f16 in, f32 accum) ----------------
#define QSTR 40
#define VSTR 72

__global__ void __launch_bounds__(128) k_attn_tc() {
    int blk = blockIdx.x;
    int n = blk / NHEADS, head = blk % NHEADS;
    int win = n % NWIN_I;

    __shared__ __half sQ[64 * QSTR];
    __shared__ __half sK[64 * QSTR];
    __shared__ __half sVt[32 * VSTR];

    int tid = threadIdx.x, lane = tid & 31, warp = tid >> 5;
    const float scale = 0.17677669529663687f;

    {
        for (int i = tid; i < 600; i += 128) {
            int r = 49 + i / 40, c = i % 40;
            sQ[r * QSTR + c] = __ushort_as_half(0);
            sK[r * QSTR + c] = __ushort_as_half(0);
        }
        for (int i = tid; i < 480; i += 128) {
            int r = i / 15, c = 49 + i % 15;
            sVt[r * VSTR + c] = __ushort_as_half(0);
        }
    }

    const __half* base = g_qkv + (size_t)n * TOK * (3*CC) + head * HD;
    for (int i = tid; i < TOK * 16; i += 128) {
        int t = i >> 4, d2 = (i & 15) * 2;
        const __half* p = base + t * (3*CC) + d2;
        float2 q2 = __half22float2(*reinterpret_cast<const __half2*>(p));
        __half2 qs = __floats2half2_rn(q2.x * scale, q2.y * scale);
        *reinterpret_cast<uint32_t*>(sQ + t * QSTR + d2) = *reinterpret_cast<uint32_t*>(&qs);
        *reinterpret_cast<uint32_t*>(sK + t * QSTR + d2) =
            *reinterpret_cast<const uint32_t*>(p + CC);
        __half2 v2 = *reinterpret_cast<const __half2*>(p + 2*CC);
        sVt[d2 * VSTR + t]       = __low2half(v2);
        sVt[(d2 + 1) * VSTR + t] = __high2half(v2);
    }
    __syncthreads();

    uint32_t sQu = smem_u32(sQ), sKu = smem_u32(sK), sVu = smem_u32(sVt);

    float sacc[8][4];
    #pragma unroll
    for (int j = 0; j < 8; j++)
        #pragma unroll
        for (int q = 0; q < 4; q++) sacc[j][q] = 0.f;

    uint32_t qAddr = sQu + ((warp * 16 + (lane & 15)) * QSTR + (lane >> 4) * 8) * 2;
    #pragma unroll
    for (int kc = 0; kc < 2; kc++) {
        uint32_t aq[4];
        ldsm_x4(aq, qAddr + kc * 32);
        #pragma unroll
        for (int jj = 0; jj < 4; jj++) {
            uint32_t bk[4];
            ldsm_x4(bk, sKu + ((jj * 16 + (lane & 15)) * QSTR + (lane >> 4) * 8 + kc * 16) * 2);
            mma16816f(sacc[jj*2 + 0], aq, bk[0], bk[2]);
            mma16816f(sacc[jj*2 + 1], aq, bk[1], bk[3]);
        }
    }

    int g = lane >> 2, qq = lane & 3;
    int r0 = warp * 16 + g, r1 = r0 + 8;
    const __half* bmrow = g_bm + (size_t)(win * NHEADS + head) * (TOK*BMS);

    float m0 = -1e30f, m1 = -1e30f;
    #pragma unroll
    for (int j = 0; j < 8; j++) {
        int t0 = j * 8 + qq * 2;
        float b00, b01, b10, b11;
        if (t0 < TOK) {
            if (r0 < TOK) {
                float2 f = __half22float2(*reinterpret_cast<const __half2*>(bmrow + r0*BMS + t0));
                b00 = f.x; b01 = f.y;
            } else { b00 = 0.f; b01 = 0.f; }
            if (r1 < TOK) {
                float2 f = __half22float2(*reinterpret_cast<const __half2*>(bmrow + r1*BMS + t0));
                b10 = f.x; b11 = f.y;
            } else { b10 = 0.f; b11 = 0.f; }
        } else {
            b00 = b01 = b10 = b11 = -1e30f;
        }
        sacc[j][0] += b00; sacc[j][1] += b01;
        sacc[j][2] += b10; sacc[j][3] += b11;
        m0 = fmaxf(m0, fmaxf(sacc[j][0], sacc[j][1]));
        m1 = fmaxf(m1, fmaxf(sacc[j][2], sacc[j][3]));
    }
    m0 = fmaxf(m0, __shfl_xor_sync(0xffffffffu, m0, 1));
    m0 = fmaxf(m0, __shfl_xor_sync(0xffffffffu, m0, 2));
    m1 = fmaxf(m1, __shfl_xor_sync(0xffffffffu, m1, 1));
    m1 = fmaxf(m1, __shfl_xor_sync(0xffffffffu, m1, 2));

    float sum0 = 0.f, sum1 = 0.f;
    #pragma unroll
    for (int j = 0; j < 8; j++) {
        sacc[j][0] = __expf(sacc[j][0] - m0);
        sacc[j][1] = __expf(sacc[j][1] - m0);
        sacc[j][2] = __expf(sacc[j][2] - m1);
        sacc[j][3] = __expf(sacc[j][3] - m1);
        sum0 += sacc[j][0] + sacc[j][1];
        sum1 += sacc[j][2] + sacc[j][3];
    }
    sum0 += __shfl_xor_sync(0xffffffffu, sum0, 1);
    sum0 += __shfl_xor_sync(0xffffffffu, sum0, 2);
    sum1 += __shfl_xor_sync(0xffffffffu, sum1, 1);
    sum1 += __shfl_xor_sync(0xffffffffu, sum1, 2);
    float inv0 = 1.0f / sum0, inv1 = 1.0f / sum1;

    uint32_t pr0[8], pr1[8];
    #pragma unroll
    for (int j = 0; j < 8; j++) {
        __half2 p0 = __floats2half2_rn(sacc[j][0] * inv0, sacc[j][1] * inv0);
        __half2 p1 = __floats2half2_rn(sacc[j][2] * inv1, sacc[j][3] * inv1);
        pr0[j] = *reinterpret_cast<uint32_t*>(&p0);
        pr1[j] = *reinterpret_cast<uint32_t*>(&p1);
    }

    float oacc[4][4];
    #pragma unroll
    for (int nt = 0; nt < 4; nt++)
        #pragma unroll
        for (int q = 0; q < 4; q++) oacc[nt][q] = 0.f;

    #pragma unroll
    for (int kk = 0; kk < 4; kk++) {
        uint32_t aP[4] = { pr0[2*kk], pr1[2*kk], pr0[2*kk+1], pr1[2*kk+1] };
        #pragma unroll
        for (int nn = 0; nn < 2; nn++) {
            uint32_t bv[4];
            ldsm_x4(bv, sVu + ((nn * 16 + (lane & 15)) * VSTR + (lane >> 4) * 8 + kk * 16) * 2);
            mma16816f(oacc[nn*2 + 0], aP, bv[0], bv[2]);
            mma16816f(oacc[nn*2 + 1], aP, bv[1], bv[3]);
        }
    }

    __half* outb = g_att + (size_t)n * TOK * CC + head * HD;
    #pragma unroll
    for (int nt = 0; nt < 4; nt++) {
        int col = nt * 8 + qq * 2;
        if (r0 < TOK) {
            __half2 o = __floats2half2_rn(oacc[nt][0], oacc[nt][1]);
            *reinterpret_cast<uint32_t*>(outb + (size_t)r0 * CC + col) =
                *reinterpret_cast<uint32_t*>(&o);
        }
        if (r1 < TOK) {
            __half2 o = __floats2half2_rn(oacc[nt][2], oacc[nt][3]);
            *reinterpret_cast<uint32_t*>(outb + (size_t)r1 * CC + col) =
                *reinterpret_cast<uint32_t*>(&o);
        }
    }
}

// ---------------- launch ----------------
extern "C" void kernel_launch(void* const* d_in, const int* in_sizes, int n_in,
                              void* d_out, int out_size) {
    const float* x       = (const float*)d_in[0];
    const float* norm1_g = (const float*)d_in[1];
    const float* norm1_b = (const float*)d_in[2];
    const float* qkv_w   = (const float*)d_in[3];
    const float* qkv_b   = (const float*)d_in[4];
    const float* rpb     = (const float*)d_in[5];
    const float* proj_w  = (const float*)d_in[6];
    const float* proj_b  = (const float*)d_in[7];
    const float* norm2_g = (const float*)d_in[8];
    const float* norm2_b = (const float*)d_in[9];
    const float* fc1_w   = (const float*)d_in[10];
    const float* fc1_b   = (const float*)d_in[11];
    const float* fc2_w   = (const float*)d_in[12];
    const float* fc2_b   = (const float*)d_in[13];
    const int*   relidx;
    const float* amask;
    if (in_sizes[14] == TOK * TOK) {
        relidx = (const int*)d_in[14];  amask = (const float*)d_in[15];
    } else {
        relidx = (const int*)d_in[15];  amask = (const float*)d_in[14];
    }
    float* out = (float*)d_out;

    __half *p_xw, *p_qkv, *p_att, *p_proj, *p_ln2, *p_hid;
    __half *p_wqkv, *p_wproj, *p_wfc1, *p_wfc2;
    cudaGetSymbolAddress((void**)&p_xw,    g_xw);
    cudaGetSymbolAddress((void**)&p_qkv,   g_qkv);
    cudaGetSymbolAddress((void**)&p_att,   g_att);
    cudaGetSymbolAddress((void**)&p_proj,  g_proj);
    cudaGetSymbolAddress((void**)&p_ln2,   g_ln2);
    cudaGetSymbolAddress((void**)&p_hid,   g_hid);
    cudaGetSymbolAddress((void**)&p_wqkv,  g_wqkv);
    cudaGetSymbolAddress((void**)&p_wproj, g_wproj);
    cudaGetSymbolAddress((void**)&p_wfc1,  g_wfc1);
    cudaGetSymbolAddress((void**)&p_wfc2,  g_wfc2);

    cudaFuncSetAttribute(k_gemm_big, cudaFuncAttributeMaxDynamicSharedMemorySize, SMEM_BIG);

    // fused prologue: LN1 + weight conversion + bias table (one launch)
    k_pre<<<PRE_BLKS, 256>>>(x, norm1_g, norm1_b, qkv_w, proj_w, fc1_w, fc2_w,
                             rpb, relidx, amask);

    // qkv: Npad=640 (5 tiles), Nreal=576
    {
        dim3 grid(640/128, NTOK/256);
        k_gemm_big<<<grid, 256, SMEM_BIG>>>(p_xw, p_wqkv, qkv_b, p_qkv, NTOK, 3*CC, CC, 0);
    }

    k_attn_tc<<<NWIN * NHEADS, 128>>>();

    // proj: Npad=256 (2 tiles), Nreal=192
    {
        dim3 grid(256/128, NTOK/256);
        k_gemm_big<<<grid, 256, SMEM_BIG>>>(p_att, p_wproj, proj_b, p_proj, NTOK, CC, CC, 0);
    }

    // LN2 only (no x1 materialization)
    k_ln2<<<NTOK/8, 256>>>(x, norm2_g, norm2_b);

    // fc1 + GELU: N=768 exact (6 tiles)
    {
        dim3 grid(HIDDEN/128, NTOK/256);
        k_gemm_big<<<grid, 256, SMEM_BIG>>>(p_ln2, p_wfc1, fc1_b, p_hid, NTOK, HIDDEN, CC, 1);
    }

    // fc2 + recomputed residual -> out (f32 accum, K=768)
    {
        dim3 grid(CC/64, NTOK/128);
        k_gemm_fc2<<<grid, 256>>>(p_hid, p_wfc2, fc2_b, x, out, NTOK, CC, HIDDEN);
    }
}

// round 17
// speedup vs baseline: 1.0310x; 1.0111x over previous
#include <cuda_runtime.h>
#include <cuda_fp16.h>
#include <math.h>
#include <stdint.h>

// ---------------- problem constants ----------------
#define BB     64
#define HH     56
#define WW     56
#define CC     192
#define NHEADS 6
#define HD     32
#define WSZ    7
#define TOK    49
#define BMS    50
#define NWIN_I 64
#define SHIFT  3
#define NTOK   (BB*HH*WW)   // 200704
#define NWIN   (BB*NWIN_I)  // 4096
#define HIDDEN 768

// ---------------- scratch (device globals; zero-initialized, no allocs allowed) ----------------
__device__ __half g_xw  [(size_t)NTOK*CC];
__device__ __half g_qkv [(size_t)NTOK*3*CC];
__device__ __half g_att [(size_t)NTOK*CC];
__device__ __half g_proj[(size_t)NTOK*CC];
__device__ __half g_ln2 [(size_t)NTOK*CC];
__device__ __half g_hid [(size_t)NTOK*HIDDEN];
__device__ __half g_wqkv [3*CC*CC];
__device__ __half g_wproj[CC*CC];
__device__ __half g_wfc1 [HIDDEN*CC];
__device__ __half g_wfc2 [CC*HIDDEN];
__device__ __half g_bm  [NWIN_I*NHEADS*TOK*BMS];

// ---------------- helpers ----------------
__device__ __forceinline__ uint32_t smem_u32(const void* p) {
    uint32_t a;
    asm("{ .reg .u64 t; cvta.to.shared.u64 t, %1; cvt.u32.u64 %0, t; }" : "=r"(a) : "l"(p));
    return a;
}
__device__ __forceinline__ float gelu_exact(float x) {
    return 0.5f * x * (1.0f + erff(x * 0.70710678118654752f));
}
__device__ __forceinline__ void ldsm_x4(uint32_t* r, uint32_t addr) {
    asm volatile("ldmatrix.sync.aligned.m8n8.x4.shared.b16 {%0,%1,%2,%3}, [%4];"
                 : "=r"(r[0]), "=r"(r[1]), "=r"(r[2]), "=r"(r[3]) : "r"(addr));
}
__device__ __forceinline__ void mma16816f(float* d, const uint32_t* a, uint32_t b0, uint32_t b1) {
    asm volatile(
        "mma.sync.aligned.m16n8k16.row.col.f32.f16.f16.f32 "
        "{%0,%1,%2,%3}, {%4,%5,%6,%7}, {%8,%9}, {%0,%1,%2,%3};"
        : "+f"(d[0]), "+f"(d[1]), "+f"(d[2]), "+f"(d[3])
        : "r"(a[0]), "r"(a[1]), "r"(a[2]), "r"(a[3]), "r"(b0), "r"(b1));
}
__device__ __forceinline__ void mma16816h(uint32_t* d, const uint32_t* a, uint32_t b0, uint32_t b1) {
    asm volatile(
        "mma.sync.aligned.m16n8k16.row.col.f16.f16.f16.f16 "
        "{%0,%1}, {%2,%3,%4,%5}, {%6,%7}, {%0,%1};"
        : "+r"(d[0]), "+r"(d[1])
        : "r"(a[0]), "r"(a[1]), "r"(a[2]), "r"(a[3]), "r"(b0), "r"(b1));
}
__device__ __forceinline__ void cpasync16(uint32_t smem, const void* gptr) {
    asm volatile("cp.async.cg.shared.global [%0], [%1], 16;" :: "r"(smem), "l"(gptr));
}
__device__ __forceinline__ void cpasync_commit() {
    asm volatile("cp.async.commit_group;" ::: "memory");
}
template<int N> __device__ __forceinline__ void cpasync_wait() {
    asm volatile("cp.async.wait_group %0;" :: "n"(N) : "memory");
}

// ---------------- fused prologue: LN1(+shift+partition) | weights f32->f16 | bias table ----------------
#define NW_QKV (3*CC*CC)
#define NW_PRJ (CC*CC)
#define NW_FC1 (HIDDEN*CC)
#define NW_FC2 (CC*HIDDEN)
#define NW_ALL (NW_QKV+NW_PRJ+NW_FC1+NW_FC2)
#define LN1_BLKS (NTOK/8)
#define F2H_BLKS ((NW_ALL + 255)/256)
#define BIAS_BLKS (NWIN_I*NHEADS)
#define PRE_BLKS (LN1_BLKS + F2H_BLKS + BIAS_BLKS)

__global__ void __launch_bounds__(256) k_pre(
        const float* __restrict__ x,
        const float* __restrict__ g, const float* __restrict__ b,
        const float* __restrict__ qkv_w, const float* __restrict__ proj_w,
        const float* __restrict__ fc1_w, const float* __restrict__ fc2_w,
        const float* __restrict__ rpb, const int* __restrict__ relidx,
        const float* __restrict__ amask) {
    int bid = blockIdx.x;
    if (bid < LN1_BLKS) {
        int lane = threadIdx.x & 31, warp = threadIdx.x >> 5;
        int w = bid * 8 + warp;
        int n = w / TOK, t = w % TOK;
        int img = n / NWIN_I, win = n % NWIN_I;
        int hs = (win / 8) * WSZ + t / WSZ;
        int ws = (win % 8) * WSZ + t % WSZ;
        int hsrc = (hs + SHIFT) % HH;
        int wsrc = (ws + SHIFT) % WW;
        const float* row = x + ((size_t)img * (HH*WW) + hsrc * WW + wsrc) * CC;

        float2 v[3];
        float s = 0.f, s2 = 0.f;
        #pragma unroll
        for (int j = 0; j < 3; j++) {
            v[j] = *reinterpret_cast<const float2*>(row + lane*2 + 64*j);
            s += v[j].x + v[j].y;
            s2 += v[j].x*v[j].x + v[j].y*v[j].y;
        }
        #pragma unroll
        for (int o = 16; o > 0; o >>= 1) {
            s  += __shfl_xor_sync(0xffffffffu, s,  o);
            s2 += __shfl_xor_sync(0xffffffffu, s2, o);
        }
        float mean = s * (1.0f / CC);
        float var  = s2 * (1.0f / CC) - mean * mean;
        float inv  = rsqrtf(var + 1e-5f);
        __half* outp = g_xw + (size_t)w * CC;
        #pragma unroll
        for (int j = 0; j < 3; j++) {
            int c = lane*2 + 64*j;
            __half2 o = __floats2half2_rn((v[j].x - mean) * inv * g[c]   + b[c],
                                          (v[j].y - mean) * inv * g[c+1] + b[c+1]);
            *reinterpret_cast<uint32_t*>(outp + c) = *reinterpret_cast<uint32_t*>(&o);
        }
        return;
    }
    bid -= LN1_BLKS;
    if (bid < F2H_BLKS) {
        int i = bid * 256 + threadIdx.x;
        if (i < NW_QKV) { g_wqkv[i] = __float2half(qkv_w[i]); return; }
        i -= NW_QKV;
        if (i < NW_PRJ) { g_wproj[i] = __float2half(proj_w[i]); return; }
        i -= NW_PRJ;
        if (i < NW_FC1) { g_wfc1[i] = __float2half(fc1_w[i]); return; }
        i -= NW_FC1;
        if (i < NW_FC2) { g_wfc2[i] = __float2half(fc2_w[i]); }
        return;
    }
    bid -= F2H_BLKS;
    {
        int win = bid / NHEADS, h = bid % NHEADS;
        for (int i = threadIdx.x; i < TOK*BMS; i += 256) {
            int r = i / BMS, t = i % BMS;
            float v = (t < TOK)
                ? rpb[relidx[r*TOK + t] * NHEADS + h] + amask[win * (TOK*TOK) + r*TOK + t]
                : -30000.0f;
            g_bm[(size_t)bid * (TOK*BMS) + i] = __float2half(v);
        }
    }
}

// ---------------- window reverse + roll + residual + LN2 (LN output ONLY) ----------------
__global__ void __launch_bounds__(256) k_ln2(const float* __restrict__ x,
                            const float* __restrict__ g,
                            const float* __restrict__ b) {
    int lane = threadIdx.x & 31, warp = threadIdx.x >> 5;
    int tok = blockIdx.x * 8 + warp;
    int img = tok / (HH*WW);
    int hw  = tok % (HH*WW);
    int hh = hw / WW, ww = hw % WW;
    int hs = (hh + HH - SHIFT) % HH;
    int ws = (ww + WW - SHIFT) % WW;
    int win = (hs / WSZ) * 8 + (ws / WSZ);
    int t   = (hs % WSZ) * WSZ + (ws % WSZ);
    const __half* prow = g_proj + ((size_t)(img * NWIN_I + win) * TOK + t) * CC;
    const float* xrow = x + (size_t)tok * CC;

    float2 v[3];
    float s = 0.f, s2 = 0.f;
    #pragma unroll
    for (int j = 0; j < 3; j++) {
        int c = lane*2 + 64*j;
        float2 xv = *reinterpret_cast<const float2*>(xrow + c);
        float2 pv = __half22float2(*reinterpret_cast<const __half2*>(prow + c));
        v[j].x = xv.x + pv.x;
        v[j].y = xv.y + pv.y;
        s += v[j].x + v[j].y;
        s2 += v[j].x*v[j].x + v[j].y*v[j].y;
    }
    #pragma unroll
    for (int o = 16; o > 0; o >>= 1) {
        s  += __shfl_xor_sync(0xffffffffu, s,  o);
        s2 += __shfl_xor_sync(0xffffffffu, s2, o);
    }
    float mean = s * (1.0f / CC);
    float var  = s2 * (1.0f / CC) - mean * mean;
    float inv  = rsqrtf(var + 1e-5f);
    __half* outp = g_ln2 + (size_t)tok * CC;
    #pragma unroll
    for (int j = 0; j < 3; j++) {
        int c = lane*2 + 64*j;
        __half2 o = __floats2half2_rn((v[j].x - mean) * inv * g[c]   + b[c],
                                      (v[j].y - mean) * inv * g[c+1] + b[c+1]);
        *reinterpret_cast<uint32_t*>(outp + c) = *reinterpret_cast<uint32_t*>(&o);
    }
}

// ---------------- BIG-TILE GEMM: BM=256, BN template (128 or 96), f16 accum ----------------
#define BSTRD 40
#define ASZ  (256*BSTRD)

template<int BN>
__global__ void __launch_bounds__(256, 2) k_gemm_big(
        const __half* __restrict__ A, const __half* __restrict__ W,
        const float* __restrict__ bias,
        __half* __restrict__ out, int M, int Nreal, int K, int gelu) {
    extern __shared__ __half smem[];
    constexpr int BSZ  = BN * BSTRD;
    constexpr int STGE = ASZ + BSZ;
    constexpr int NT   = BN / 16;           // n8-tile pairs per warp (8 or 6)
    constexpr int NL   = BN / 32;           // B ldsm per k-step (4 or 3)
    constexpr int WN   = BN / 2;            // warp n-tile (64 or 48)
    constexpr int BCP  = (BN * 24) / 256;   // B cp.async per thread per chunk (12 or 9)

    int tid = threadIdx.x, lane = tid & 31, wid = tid >> 5;
    int warp_m = wid & 3, warp_n = wid >> 2;
    int gm0 = blockIdx.y * 256;
    int gn0 = blockIdx.x * BN;

    uint32_t acch[4][NT][2];
    #pragma unroll
    for (int mi = 0; mi < 4; mi++)
        #pragma unroll
        for (int nt = 0; nt < NT; nt++) { acch[mi][nt][0] = 0u; acch[mi][nt][1] = 0u; }

    uint32_t sb = smem_u32(smem);
    int lr = tid >> 2, lc = (tid & 3) * 8;

    const __half* Ag = A + (size_t)(gm0 + lr) * K + lc;
    uint32_t sa_w = sb + (lr * BSTRD + lc) * 2;

    int nk = K >> 5;
    #pragma unroll
    for (int s = 0; s < 2; s++) {
        uint32_t so = s * STGE * 2;
        #pragma unroll
        for (int j = 0; j < 4; j++)
            cpasync16(sa_w + so + j * 64 * BSTRD * 2, Ag + s * 32 + (size_t)(j * 64) * K);
        #pragma unroll
        for (int j = 0; j < BCP; j++) {
            int i = tid + 256 * j;
            int r = i / 24, c = i % 24;
            cpasync16(sb + (s * STGE + ASZ + r * BSTRD + c * 8) * 2,
                      W + (size_t)(gn0 + r) * K + s * 32 + (c & 3) * 8);
            (void)c;
        }
        cpasync_commit();
    }
    // NOTE: B column index within 32-wide chunk: c ranges 0..23 covering 192? No — per
    // chunk we only need 32 cols = 4 col-groups of 8. Fix below uses r,cg mapping.

    int st = 0;
    for (int ch = 0; ch < nk; ch++) {
        if (ch + 1 < nk) cpasync_wait<1>(); else cpasync_wait<0>();
        __syncthreads();
        if (ch + 2 < nk) {
            int st2 = st + 2; if (st2 >= 3) st2 -= 3;
            uint32_t so = st2 * STGE * 2;
            const __half* Ag2 = Ag + (ch + 2) * 32;
            #pragma unroll
            for (int j = 0; j < 4; j++)
                cpasync16(sa_w + so + j * 64 * BSTRD * 2, Ag2 + (size_t)(j * 64) * K);
            #pragma unroll
            for (int j = 0; j < BN/64; j++) {
                int r = lr + j * 64;
                cpasync16(sb + (st2 * STGE + ASZ + r * BSTRD + lc) * 2,
                          W + (size_t)(gn0 + r) * K + (ch + 2) * 32 + lc);
            }
            if (BN == 96) {
                // remaining 32 rows (64..95): threads 0..127 cover 32 rows x 4 col-groups
                if (tid < 128) {
                    int r = 64 + (tid >> 2), c = (tid & 3) * 8;
                    cpasync16(sb + (st2 * STGE + ASZ + r * BSTRD + c) * 2,
                              W + (size_t)(gn0 + r) * K + (ch + 2) * 32 + c);
                }
            }
            cpasync_commit();
        }

        uint32_t aAddr = sb + (st * STGE + (warp_m * 64 + (lane & 15)) * BSTRD + (lane >> 4) * 8) * 2;
        uint32_t bAddr = sb + (st * STGE + ASZ + (warp_n * WN + (lane & 15)) * BSTRD + (lane >> 4) * 8) * 2;
        #pragma unroll
        for (int ks = 0; ks < 2; ks++) {
            uint32_t a[4][4], b[NL][4];
            #pragma unroll
            for (int mi = 0; mi < 4; mi++)
                ldsm_x4(a[mi], aAddr + (mi * 16 * BSTRD + ks * 16) * 2);
            #pragma unroll
            for (int g = 0; g < NL; g++)
                ldsm_x4(b[g], bAddr + (g * 16 * BSTRD + ks * 16) * 2);
            #pragma unroll
            for (int mi = 0; mi < 4; mi++)
                #pragma unroll
                for (int nt = 0; nt < NT; nt++)
                    mma16816h(acch[mi][nt], a[mi], b[nt >> 1][nt & 1], b[nt >> 1][2 + (nt & 1)]);
        }
        if (++st == 3) st = 0;
    }

    int row_base = gm0 + warp_m * 64 + (lane >> 2);
    int col_base = gn0 + warp_n * WN + (lane & 3) * 2;

    #pragma unroll
    for (int mi = 0; mi < 4; mi++) {
        #pragma unroll
        for (int nt = 0; nt < NT; nt++) {
            int col = col_base + nt * 8;
            if (col >= Nreal) continue;
            float bc0 = bias[col], bc1 = bias[col + 1];
            #pragma unroll
            for (int h = 0; h < 2; h++) {
                int r = row_base + mi * 16 + h * 8;
                __half2 hh = *reinterpret_cast<__half2*>(&acch[mi][nt][h]);
                float2 f = __half22float2(hh);
                float v0 = f.x + bc0, v1 = f.y + bc1;
                if (gelu) { v0 = gelu_exact(v0); v1 = gelu_exact(v1); }
                __half2 p = __floats2half2_rn(v0, v1);
                *reinterpret_cast<uint32_t*>(out + (size_t)r * Nreal + col) =
                    *reinterpret_cast<uint32_t*>(&p);
            }
        }
    }
}

// prologue B-load fix: the generic j-loop above for the prologue is wrong for col
// addressing; re-specialize prologue B loads identically to the steady-state form.
// (Handled by using the same per-row mapping: see k_gemm_big2 below.)
// To keep one proven code path, we instead define the kernel again cleanly:

template<int BN>
__global__ void __launch_bounds__(256, 2) k_gemm_bigN(
        const __half* __restrict__ A, const __half* __restrict__ W,
        const float* __restrict__ bias,
        __half* __restrict__ out, int M, int Nreal, int K, int gelu) {
    extern __shared__ __half smem[];
    constexpr int BSZ  = BN * BSTRD;
    constexpr int STGE = ASZ + BSZ;
    constexpr int NT   = BN / 16;
    constexpr int NL   = BN / 32;
    constexpr int WN   = BN / 2;

    int tid = threadIdx.x, lane = tid & 31, wid = tid >> 5;
    int warp_m = wid & 3, warp_n = wid >> 2;
    int gm0 = blockIdx.y * 256;
    int gn0 = blockIdx.x * BN;

    uint32_t acch[4][NT][2];
    #pragma unroll
    for (int mi = 0; mi < 4; mi++)
        #pragma unroll
        for (int nt = 0; nt < NT; nt++) { acch[mi][nt][0] = 0u; acch[mi][nt][1] = 0u; }

    uint32_t sb = smem_u32(smem);
    int lr = tid >> 2, lc = (tid & 3) * 8;

    const __half* Ag = A + (size_t)(gm0 + lr) * K + lc;
    const __half* Wg = W + (size_t)(gn0 + lr) * K + lc;
    uint32_t sa_w = sb + (lr * BSTRD + lc) * 2;
    uint32_t sb_w = sb + (ASZ + lr * BSTRD + lc) * 2;

    int nk = K >> 5;
    #pragma unroll
    for (int s = 0; s < 2; s++) {
        uint32_t so = s * STGE * 2;
        #pragma unroll
        for (int j = 0; j < 4; j++)
            cpasync16(sa_w + so + j * 64 * BSTRD * 2, Ag + s * 32 + (size_t)(j * 64) * K);
        #pragma unroll
        for (int j = 0; j < BN/64; j++)
            cpasync16(sb_w + so + j * 64 * BSTRD * 2, Wg + s * 32 + (size_t)(j * 64) * K);
        if (BN == 96) {
            if (tid < 128) {
                int r = 64 + (tid >> 2), c = (tid & 3) * 8;
                cpasync16(sb + (s * STGE + ASZ + r * BSTRD + c) * 2,
                          W + (size_t)(gn0 + r) * K + s * 32 + c);
            }
        }
        cpasync_commit();
    }

    int st = 0;
    for (int ch = 0; ch < nk; ch++) {
        if (ch + 1 < nk) cpasync_wait<1>(); else cpasync_wait<0>();
        __syncthreads();
        if (ch + 2 < nk) {
            int st2 = st + 2; if (st2 >= 3) st2 -= 3;
            uint32_t so = st2 * STGE * 2;
            const __half* Ag2 = Ag + (ch + 2) * 32;
            const __half* Wg2 = Wg + (ch + 2) * 32;
            #pragma unroll
            for (int j = 0; j < 4; j++)
                cpasync16(sa_w + so + j * 64 * BSTRD * 2, Ag2 + (size_t)(j * 64) * K);
            #pragma unroll
            for (int j = 0; j < BN/64; j++)
                cpasync16(sb_w + so + j * 64 * BSTRD * 2, Wg2 + (size_t)(j * 64) * K);
            if (BN == 96) {
                if (tid < 128) {
                    int r = 64 + (tid >> 2), c = (tid & 3) * 8;
                    cpasync16(sb + (st2 * STGE + ASZ + r * BSTRD + c) * 2,
                              W + (size_t)(gn0 + r) * K + (ch + 2) * 32 + c);
                }
            }
            cpasync_commit();
        }

        uint32_t aAddr = sb + (st * STGE + (warp_m * 64 + (lane & 15)) * BSTRD + (lane >> 4) * 8) * 2;
        uint32_t bAddr = sb + (st * STGE + ASZ + (warp_n * WN + (lane & 15)) * BSTRD + (lane >> 4) * 8) * 2;
        #pragma unroll
        for (int ks = 0; ks < 2; ks++) {
            uint32_t a[4][4], b[NL][4];
            #pragma unroll
            for (int mi = 0; mi < 4; mi++)
                ldsm_x4(a[mi], aAddr + (mi * 16 * BSTRD + ks * 16) * 2);
            #pragma unroll
            for (int g = 0; g < NL; g++)
                ldsm_x4(b[g], bAddr + (g * 16 * BSTRD + ks * 16) * 2);
            #pragma unroll
            for (int mi = 0; mi < 4; mi++)
                #pragma unroll
                for (int nt = 0; nt < NT; nt++)
                    mma16816h(acch[mi][nt], a[mi], b[nt >> 1][nt & 1], b[nt >> 1][2 + (nt & 1)]);
        }
        if (++st == 3) st = 0;
    }

    int row_base = gm0 + warp_m * 64 + (lane >> 2);
    int col_base = gn0 + warp_n * WN + (lane & 3) * 2;

    #pragma unroll
    for (int mi = 0; mi < 4; mi++) {
        #pragma unroll
        for (int nt = 0; nt < NT; nt++) {
            int col = col_base + nt * 8;
            if (col >= Nreal) continue;
            float bc0 = bias[col], bc1 = bias[col + 1];
            #pragma unroll
            for (int h = 0; h < 2; h++) {
                int r = row_base + mi * 16 + h * 8;
                __half2 hh = *reinterpret_cast<__half2*>(&acch[mi][nt][h]);
                float2 f = __half22float2(hh);
                float v0 = f.x + bc0, v1 = f.y + bc1;
                if (gelu) { v0 = gelu_exact(v0); v1 = gelu_exact(v1); }
                __half2 p = __floats2half2_rn(v0, v1);
                *reinterpret_cast<uint32_t*>(out + (size_t)r * Nreal + col) =
                    *reinterpret_cast<uint32_t*>(&p);
            }
        }
    }
}

// ---------------- fc2 GEMM: 128x64, f32 accum, 3-stage; epilogue recomputes residual ----------------
#define ASTR 40
#define BSTR 40
#define A_ST (128*ASTR)
#define B_ST (64*BSTR)

__global__ void __launch_bounds__(256, 3) k_gemm_fc2(
        const __half* __restrict__ A, const __half* __restrict__ W,
        const float* __restrict__ bias, const float* __restrict__ x,
        float* __restrict__ out, int M, int N, int K) {
    __shared__ __half sA[3*A_ST];
    __shared__ __half sB[3*B_ST];

    int tid = threadIdx.x, lane = tid & 31, wid = tid >> 5;
    int warp_m = wid & 3, warp_n = wid >> 2;
    int gm0 = blockIdx.y * 128;
    int gn0 = blockIdx.x * 64;

    float accf[2][4][4];
    #pragma unroll
    for (int mi = 0; mi < 2; mi++)
        #pragma unroll
        for (int ni = 0; ni < 4; ni++)
            #pragma unroll
            for (int q = 0; q < 4; q++) accf[mi][ni][q] = 0.f;

    uint32_t sAu = smem_u32(sA), sBu = smem_u32(sB);
    int lrA = tid >> 2, lcA = (tid & 3) * 8;

    const __half* Ag = A + (size_t)(gm0 + lrA) * K + lcA;
    const __half* Wg = W + (size_t)(gn0 + lrA) * K + lcA;
    uint32_t sa_w = sAu + (lrA * ASTR + lcA) * 2;
    uint32_t sb_w = sBu + (lrA * BSTR + lcA) * 2;

    int nk = K >> 5;
    #pragma unroll
    for (int s = 0; s < 2; s++) {
        cpasync16(sa_w + s * A_ST * 2,             Ag + s * 32);
        cpasync16(sa_w + (s * A_ST + 64*ASTR) * 2, Ag + s * 32 + (size_t)64 * K);
        cpasync16(sb_w + s * B_ST * 2,             Wg + s * 32);
        cpasync_commit();
    }

    int st = 0;
    for (int ch = 0; ch < nk; ch++) {
        if (ch + 1 < nk) cpasync_wait<1>(); else cpasync_wait<0>();
        __syncthreads();
        if (ch + 2 < nk) {
            int st2 = st + 2; if (st2 >= 3) st2 -= 3;
            const __half* Ag2 = Ag + (ch + 2) * 32;
            const __half* Wg2 = Wg + (ch + 2) * 32;
            cpasync16(sa_w + st2 * A_ST * 2,             Ag2);
            cpasync16(sa_w + (st2 * A_ST + 64*ASTR) * 2, Ag2 + (size_t)64 * K);
            cpasync16(sb_w + st2 * B_ST * 2,             Wg2);
            cpasync_commit();
        }

        uint32_t aAddr = sAu + (st * A_ST + (warp_m * 32 + (lane & 15)) * ASTR + (lane >> 4) * 8) * 2;
        uint32_t bAddr = sBu + (st * B_ST + (warp_n * 32 + (lane & 15)) * BSTR + (lane >> 4) * 8) * 2;
        #pragma unroll
        for (int ks = 0; ks < 2; ks++) {
            uint32_t a[2][4], b[2][4];
            #pragma unroll
            for (int mi = 0; mi < 2; mi++)
                ldsm_x4(a[mi], aAddr + (mi * 16 * ASTR + ks * 16) * 2);
            #pragma unroll
            for (int nj = 0; nj < 2; nj++)
                ldsm_x4(b[nj], bAddr + (nj * 16 * BSTR + ks * 16) * 2);
            #pragma unroll
            for (int mi = 0; mi < 2; mi++)
                #pragma unroll
                for (int ni = 0; ni < 4; ni++)
                    mma16816f(accf[mi][ni], a[mi], b[ni >> 1][ni & 1], b[ni >> 1][2 + (ni & 1)]);
        }
        if (++st == 3) st = 0;
    }

    int row_base = gm0 + warp_m * 32 + (lane >> 2);
    int col_base = gn0 + warp_n * 32 + (lane & 3) * 2;

    size_t pbase[2][2];
    #pragma unroll
    for (int mi = 0; mi < 2; mi++)
        #pragma unroll
        for (int h = 0; h < 2; h++) {
            int r = row_base + mi * 16 + h * 8;
            int img = r / (HH*WW);
            int hw  = r % (HH*WW);
            int hh = hw / WW, ww = hw % WW;
            int hs = (hh + HH - SHIFT) % HH;
            int ws = (ww + WW - SHIFT) % WW;
            int win = (hs / WSZ) * 8 + (ws / WSZ);
            int t   = (hs % WSZ) * WSZ + (ws % WSZ);
            pbase[mi][h] = ((size_t)(img * NWIN_I + win) * TOK + t) * CC;
        }

    #pragma unroll
    for (int mi = 0; mi < 2; mi++) {
        #pragma unroll
        for (int ni = 0; ni < 4; ni++) {
            int col = col_base + ni * 8;
            float bc0 = bias[col], bc1 = bias[col + 1];
            #pragma unroll
            for (int h = 0; h < 2; h++) {
                int r = row_base + mi * 16 + h * 8;
                float v0 = accf[mi][ni][h * 2 + 0] + bc0;
                float v1 = accf[mi][ni][h * 2 + 1] + bc1;
                const float2 xv = *reinterpret_cast<const float2*>(x + (size_t)r * N + col);
                float2 pv = __half22float2(
                    *reinterpret_cast<const __half2*>(g_proj + pbase[mi][h] + col));
                float2 o;
                o.x = v0 + xv.x + pv.x;
                o.y = v1 + xv.y + pv.y;
                *reinterpret_cast<float2*>(out + (size_t)r * N + col) = o;
            }
        }
    }
}

// ---------------- tensor-core windowed attention (f16 in, f32 accum) ----------------
#define QSTR 40
#define VSTR 72

__global__ void __launch_bounds__(128) k_attn_tc() {
    int blk = blockIdx.x;
    int n = blk / NHEADS, head = blk % NHEADS;
    int win = n % NWIN_I;

    __shared__ __half sQ[64 * QSTR];
    __shared__ __half sK[64 * QSTR];
    __shared__ __half sVt[32 * VSTR];

    int tid = threadIdx.x, lane = tid & 31, warp = tid >> 5;
    const float scale = 0.17677669529663687f;

    {
        for (int i = tid; i < 600; i += 128) {
            int r = 49 + i / 40, c = i % 40;
            sQ[r * QSTR + c] = __ushort_as_half(0);
            sK[r * QSTR + c] = __ushort_as_half(0);
        }
        for (int i = tid; i < 480; i += 128) {
            int r = i / 15, c = 49 + i % 15;
            sVt[r * VSTR + c] = __ushort_as_half(0);
        }
    }

    const __half* base = g_qkv + (size_t)n * TOK * (3*CC) + head * HD;
    for (int i = tid; i < TOK * 16; i += 128) {
        int t = i >> 4, d2 = (i & 15) * 2;
        const __half* p = base + t * (3*CC) + d2;
        float2 q2 = __half22float2(*reinterpret_cast<const __half2*>(p));
        __half2 qs = __floats2half2_rn(q2.x * scale, q2.y * scale);
        *reinterpret_cast<uint32_t*>(sQ + t * QSTR + d2) = *reinterpret_cast<uint32_t*>(&qs);
        *reinterpret_cast<uint32_t*>(sK + t * QSTR + d2) =
            *reinterpret_cast<const uint32_t*>(p + CC);
        __half2 v2 = *reinterpret_cast<const __half2*>(p + 2*CC);
        sVt[d2 * VSTR + t]       = __low2half(v2);
        sVt[(d2 + 1) * VSTR + t] = __high2half(v2);
    }
    __syncthreads();

    uint32_t sQu = smem_u32(sQ), sKu = smem_u32(sK), sVu = smem_u32(sVt);

    float sacc[8][4];
    #pragma unroll
    for (int j = 0; j < 8; j++)
        #pragma unroll
        for (int q = 0; q < 4; q++) sacc[j][q] = 0.f;

    uint32_t qAddr = sQu + ((warp * 16 + (lane & 15)) * QSTR + (lane >> 4) * 8) * 2;
    #pragma unroll
    for (int kc = 0; kc < 2; kc++) {
        uint32_t aq[4];
        ldsm_x4(aq, qAddr + kc * 32);
        #pragma unroll
        for (int jj = 0; jj < 4; jj++) {
            uint32_t bk[4];
            ldsm_x4(bk, sKu + ((jj * 16 + (lane & 15)) * QSTR + (lane >> 4) * 8 + kc * 16) * 2);
            mma16816f(sacc[jj*2 + 0], aq, bk[0], bk[2]);
            mma16816f(sacc[jj*2 + 1], aq, bk[1], bk[3]);
        }
    }

    int g = lane >> 2, qq = lane & 3;
    int r0 = warp * 16 + g, r1 = r0 + 8;
    const __half* bmrow = g_bm + (size_t)(win * NHEADS + head) * (TOK*BMS);

    float m0 = -1e30f, m1 = -1e30f;
    #pragma unroll
    for (int j = 0; j < 8; j++) {
        int t0 = j * 8 + qq * 2;
        float b00, b01, b10, b11;
        if (t0 < TOK) {
            if (r0 < TOK) {
                float2 f = __half22float2(*reinterpret_cast<const __half2*>(bmrow + r0*BMS + t0));
                b00 = f.x; b01 = f.y;
            } else { b00 = 0.f; b01 = 0.f; }
            if (r1 < TOK) {
                float2 f = __half22float2(*reinterpret_cast<const __half2*>(bmrow + r1*BMS + t0));
                b10 = f.x; b11 = f.y;
            } else { b10 = 0.f; b11 = 0.f; }
        } else {
            b00 = b01 = b10 = b11 = -1e30f;
        }
        sacc[j][0] += b00; sacc[j][1] += b01;
        sacc[j][2] += b10; sacc[j][3] += b11;
        m0 = fmaxf(m0, fmaxf(sacc[j][0], sacc[j][1]));
        m1 = fmaxf(m1, fmaxf(sacc[j][2], sacc[j][3]));
    }
    m0 = fmaxf(m0, __shfl_xor_sync(0xffffffffu, m0, 1));
    m0 = fmaxf(m0, __shfl_xor_sync(0xffffffffu, m0, 2));
    m1 = fmaxf(m1, __shfl_xor_sync(0xffffffffu, m1, 1));
    m1 = fmaxf(m1, __shfl_xor_sync(0xffffffffu, m1, 2));

    float sum0 = 0.f, sum1 = 0.f;
    #pragma unroll
    for (int j = 0; j < 8; j++) {
        sacc[j][0] = __expf(sacc[j][0] - m0);
        sacc[j][1] = __expf(sacc[j][1] - m0);
        sacc[j][2] = __expf(sacc[j][2] - m1);
        sacc[j][3] = __expf(sacc[j][3] - m1);
        sum0 += sacc[j][0] + sacc[j][1];
        sum1 += sacc[j][2] + sacc[j][3];
    }
    sum0 += __shfl_xor_sync(0xffffffffu, sum0, 1);
    sum0 += __shfl_xor_sync(0xffffffffu, sum0, 2);
    sum1 += __shfl_xor_sync(0xffffffffu, sum1, 1);
    sum1 += __shfl_xor_sync(0xffffffffu, sum1, 2);
    float inv0 = 1.0f / sum0, inv1 = 1.0f / sum1;

    uint32_t pr0[8], pr1[8];
    #pragma unroll
    for (int j = 0; j < 8; j++) {
        __half2 p0 = __floats2half2_rn(sacc[j][0] * inv0, sacc[j][1] * inv0);
        __half2 p1 = __floats2half2_rn(sacc[j][2] * inv1, sacc[j][3] * inv1);
        pr0[j] = *reinterpret_cast<uint32_t*>(&p0);
        pr1[j] = *reinterpret_cast<uint32_t*>(&p1);
    }

    float oacc[4][4];
    #pragma unroll
    for (int nt = 0; nt < 4; nt++)
        #pragma unroll
        for (int q = 0; q < 4; q++) oacc[nt][q] = 0.f;

    #pragma unroll
    for (int kk = 0; kk < 4; kk++) {
        uint32_t aP[4] = { pr0[2*kk], pr1[2*kk], pr0[2*kk+1], pr1[2*kk+1] };
        #pragma unroll
        for (int nn = 0; nn < 2; nn++) {
            uint32_t bv[4];
            ldsm_x4(bv, sVu + ((nn * 16 + (lane & 15)) * VSTR + (lane >> 4) * 8 + kk * 16) * 2);
            mma16816f(oacc[nn*2 + 0], aP, bv[0], bv[2]);
            mma16816f(oacc[nn*2 + 1], aP, bv[1], bv[3]);
        }
    }

    __half* outb = g_att + (size_t)n * TOK * CC + head * HD;
    #pragma unroll
    for (int nt = 0; nt < 4; nt++) {
        int col = nt * 8 + qq * 2;
        if (r0 < TOK) {
            __half2 o = __floats2half2_rn(oacc[nt][0], oacc[nt][1]);
            *reinterpret_cast<uint32_t*>(outb + (size_t)r0 * CC + col) =
                *reinterpret_cast<uint32_t*>(&o);
        }
        if (r1 < TOK) {
            __half2 o = __floats2half2_rn(oacc[nt][2], oacc[nt][3]);
            *reinterpret_cast<uint32_t*>(outb + (size_t)r1 * CC + col) =
                *reinterpret_cast<uint32_t*>(&o);
        }
    }
}

// ---------------- launch ----------------
#define SMEM_BN(BN) (3 * (ASZ + (BN)*BSTRD) * 2)

extern "C" void kernel_launch(void* const* d_in, const int* in_sizes, int n_in,
                              void* d_out, int out_size) {
    const float* x       = (const float*)d_in[0];
    const float* norm1_g = (const float*)d_in[1];
    const float* norm1_b = (const float*)d_in[2];
    const float* qkv_w   = (const float*)d_in[3];
    const float* qkv_b   = (const float*)d_in[4];
    const float* rpb     = (const float*)d_in[5];
    const float* proj_w  = (const float*)d_in[6];
    const float* proj_b  = (const float*)d_in[7];
    const float* norm2_g = (const float*)d_in[8];
    const float* norm2_b = (const float*)d_in[9];
    const float* fc1_w   = (const float*)d_in[10];
    const float* fc1_b   = (const float*)d_in[11];
    const float* fc2_w   = (const float*)d_in[12];
    const float* fc2_b   = (const float*)d_in[13];
    const int*   relidx;
    const float* amask;
    if (in_sizes[14] == TOK * TOK) {
        relidx = (const int*)d_in[14];  amask = (const float*)d_in[15];
    } else {
        relidx = (const int*)d_in[15];  amask = (const float*)d_in[14];
    }
    float* out = (float*)d_out;

    __half *p_xw, *p_qkv, *p_att, *p_proj, *p_ln2, *p_hid;
    __half *p_wqkv, *p_wproj, *p_wfc1, *p_wfc2;
    cudaGetSymbolAddress((void**)&p_xw,    g_xw);
    cudaGetSymbolAddress((void**)&p_qkv,   g_qkv);
    cudaGetSymbolAddress((void**)&p_att,   g_att);
    cudaGetSymbolAddress((void**)&p_proj,  g_proj);
    cudaGetSymbolAddress((void**)&p_ln2,   g_ln2);
    cudaGetSymbolAddress((void**)&p_hid,   g_hid);
    cudaGetSymbolAddress((void**)&p_wqkv,  g_wqkv);
    cudaGetSymbolAddress((void**)&p_wproj, g_wproj);
    cudaGetSymbolAddress((void**)&p_wfc1,  g_wfc1);
    cudaGetSymbolAddress((void**)&p_wfc2,  g_wfc2);

    cudaFuncSetAttribute(k_gemm_bigN<128>, cudaFuncAttributeMaxDynamicSharedMemorySize, SMEM_BN(128));
    cudaFuncSetAttribute(k_gemm_bigN<96>,  cudaFuncAttributeMaxDynamicSharedMemorySize, SMEM_BN(96));

    // fused prologue
    k_pre<<<PRE_BLKS, 256>>>(x, norm1_g, norm1_b, qkv_w, proj_w, fc1_w, fc2_w,
                             rpb, relidx, amask);

    // qkv: N=576 exact with BN=96 (6 tiles)
    {
        dim3 grid(6, NTOK/256);
        k_gemm_bigN<96><<<grid, 256, SMEM_BN(96)>>>(p_xw, p_wqkv, qkv_b, p_qkv, NTOK, 3*CC, CC, 0);
    }

    k_attn_tc<<<NWIN * NHEADS, 128>>>();

    // proj: N=192 exact with BN=96 (2 tiles)
    {
        dim3 grid(2, NTOK/256);
        k_gemm_bigN<96><<<grid, 256, SMEM_BN(96)>>>(p_att, p_wproj, proj_b, p_proj, NTOK, CC, CC, 0);
    }

    k_ln2<<<NTOK/8, 256>>>(x, norm2_g, norm2_b);

    // fc1 + GELU: N=768 exact with BN=128 (6 tiles)
    {
        dim3 grid(6, NTOK/256);
        k_gemm_bigN<128><<<grid, 256, SMEM_BN(128)>>>(p_ln2, p_wfc1, fc1_b, p_hid, NTOK, HIDDEN, CC, 1);
    }

    // fc2 + recomputed residual -> out
    {
        dim3 grid(CC/64, NTOK/128);
        k_gemm_fc2<<<grid, 256>>>(p_hid, p_wfc2, fc2_b, x, out, NTOK, CC, HIDDEN);
    }
}